// round 8
// baseline (speedup 1.0000x reference)
#include <cuda_runtime.h>
#include <cuda_bf16.h>
#include <cstdint>

#define Bn   8
#define Cn   256
#define Kn   9
#define Hn   64
#define Wn   64
#define HWn  (Hn*Wn)       // 4096
#define NPIX (Bn*HWn)      // 32768

// ---- scratch (device globals; no allocation allowed) ----
__device__ float g_key_t[(size_t)Bn*HWn*Cn];          // [B][HW][C] transposed key
__device__ __nv_bfloat16 g_sh[(size_t)NPIX*Cn];       // sampled features, bf16 hi
__device__ __nv_bfloat16 g_sl[(size_t)NPIX*Cn];       // sampled features, bf16 lo
__device__ __nv_bfloat16 g_wh[Cn*Cn];                 // w_refer hi
__device__ __nv_bfloat16 g_wl[Cn*Cn];                 // w_refer lo
__device__ float g_aw[Bn*Kn*HWn];
__device__ float g_dy[Bn*Kn*HWn];
__device__ float g_dx[Bn*Kn*HWn];
__device__ float g_g[NPIX];                            // bias weight-sum per pixel

// ================= helpers =================
__device__ __forceinline__ uint32_t smem_u32(const void* p) {
    uint32_t a;
    asm("{ .reg .u64 t; cvta.to.shared.u64 t, %1; cvt.u32.u64 %0, t; }" : "=r"(a) : "l"(p));
    return a;
}
__device__ __forceinline__ uint32_t lds32(uint32_t a) {
    uint32_t v;
    asm volatile("ld.shared.b32 %0, [%1];" : "=r"(v) : "r"(a));
    return v;
}
__device__ __forceinline__ void ldmatrix_x4(uint32_t& r0, uint32_t& r1,
                                            uint32_t& r2, uint32_t& r3, uint32_t a) {
    asm volatile("ldmatrix.sync.aligned.m8n8.x4.shared.b16 {%0,%1,%2,%3}, [%4];"
                 : "=r"(r0), "=r"(r1), "=r"(r2), "=r"(r3) : "r"(a));
}
__device__ __forceinline__ void mma16816(float* c, uint32_t a0, uint32_t a1,
                                         uint32_t a2, uint32_t a3,
                                         uint32_t b0, uint32_t b1) {
    asm volatile(
        "mma.sync.aligned.m16n8k16.row.col.f32.bf16.bf16.f32 "
        "{%0,%1,%2,%3}, {%4,%5,%6,%7}, {%8,%9}, {%0,%1,%2,%3};"
        : "+f"(c[0]), "+f"(c[1]), "+f"(c[2]), "+f"(c[3])
        : "r"(a0), "r"(a1), "r"(a2), "r"(a3), "r"(b0), "r"(b1));
}
__device__ __forceinline__ void cp16(uint32_t s, const void* g) {
    asm volatile("cp.async.cg.shared.global [%0], [%1], 16;" :: "r"(s), "l"(g));
}
__device__ __forceinline__ void cp_commit() {
    asm volatile("cp.async.commit_group;" ::: "memory");
}
template<int N> __device__ __forceinline__ void cp_wait() {
    asm volatile("cp.async.wait_group %0;" :: "n"(N) : "memory");
}

// ============================================================
// K1: transpose key_layer [B,C,HW] -> g_key_t [B,HW,C]
// ============================================================
__global__ void k_transpose(const float* __restrict__ key) {
    __shared__ float t[32][33];
    int b   = blockIdx.z;
    int hw0 = blockIdx.x * 32;
    int c0  = blockIdx.y * 32;
    int tx = threadIdx.x, ty = threadIdx.y;
    const float* src = key + (size_t)b * Cn * HWn;
    #pragma unroll
    for (int i = 0; i < 4; i++)
        t[ty + i*8][tx] = src[(size_t)(c0 + ty + i*8) * HWn + hw0 + tx];
    __syncthreads();
    float* dst = g_key_t + (size_t)b * HWn * Cn;
    #pragma unroll
    for (int i = 0; i < 4; i++)
        dst[(size_t)(hw0 + ty + i*8) * Cn + c0 + tx] = t[tx][ty + i*8];
}

// ============================================================
// K2: per-pixel params, split-C across two thread groups.
// ============================================================
__global__ void __launch_bounds__(256)
k_params(const float* __restrict__ query,
         const float* __restrict__ gmb,
         const float* __restrict__ b_attn,
         const float* __restrict__ b_mask,
         const float* __restrict__ b_off,
         const float* __restrict__ w_attn,
         const float* __restrict__ w_mask,
         const float* __restrict__ w_off,
         const unsigned* __restrict__ temp_raw) {
    __shared__ float4 sW[28*64];
    __shared__ float  sB[28];
    __shared__ float  sPart[128*29];
    int tid = threadIdx.x;
    for (int i = tid; i < 576; i += 256) sW[i]        = ((const float4*)w_attn)[i];
    for (int i = tid; i < 576; i += 256) sW[576 + i]  = ((const float4*)w_mask)[i];
    for (int i = tid; i < 640; i += 256) sW[1152 + i] = ((const float4*)w_off)[i];
    if (tid < 9)  { sB[tid] = b_attn[tid]; sB[9 + tid] = b_mask[tid]; }
    if (tid < 10) sB[18 + tid] = b_off[tid];
    __syncthreads();

    int lp = tid & 127, ph = tid >> 7;
    int pix = blockIdx.x * 128 + lp;
    int b  = pix >> 12;
    int hw = pix & (HWn - 1);

    const float* q = query + (size_t)b * Cn * HWn + (size_t)(ph*128) * HWn + hw;
    float acc[28];
    #pragma unroll
    for (int r = 0; r < 28; r++) acc[r] = 0.f;

    #pragma unroll 4
    for (int c4 = 0; c4 < 32; c4++) {
        float q0 = q[(c4*4 + 0) * HWn];
        float q1 = q[(c4*4 + 1) * HWn];
        float q2 = q[(c4*4 + 2) * HWn];
        float q3 = q[(c4*4 + 3) * HWn];
        #pragma unroll
        for (int r = 0; r < 28; r++) {
            float4 w = sW[r*64 + ph*32 + c4];
            acc[r] += q0*w.x + q1*w.y + q2*w.z + q3*w.w;
        }
    }

    if (ph == 1) {
        #pragma unroll
        for (int r = 0; r < 28; r++) sPart[lp*29 + r] = acc[r];
    }
    __syncthreads();
    if (ph == 1) return;

    #pragma unroll
    for (int r = 0; r < 28; r++) acc[r] += sPart[lp*29 + r];

    unsigned lo = temp_raw[0];
    float t;
    if      (lo == 1u)           t = 1.f;
    else if (lo == 0x3F800000u)  t = 1.f;
    else if (lo == 0u)           t = 1.f;
    else                         t = __uint_as_float(lo);
    float invt = 1.f / t;

    float mv[9]; float mx = -3.4e38f;
    #pragma unroll
    for (int k = 0; k < 9; k++) {
        float gk = gmb[(size_t)(b*Kn + k) * HWn + hw];
        mv[k] = (acc[9 + k] + sB[9 + k] + gk) * invt;
        mx = fmaxf(mx, mv[k]);
    }
    float sum = 0.f;
    #pragma unroll
    for (int k = 0; k < 9; k++) { mv[k] = expf(mv[k] - mx); sum += mv[k]; }
    float rs = 1.f / sum;

    float z[9]; float mx2 = -3.4e38f;
    #pragma unroll
    for (int k = 0; k < 9; k++) {
        z[k] = (acc[k] + sB[k]) * (mv[k] * rs);
        mx2 = fmaxf(mx2, z[k]);
    }
    float sum2 = 0.f;
    #pragma unroll
    for (int k = 0; k < 9; k++) { z[k] = expf(z[k] - mx2); sum2 += z[k]; }
    float rs2 = 1.f / sum2;

    #pragma unroll
    for (int k = 0; k < 9; k++) {
        int o = (b*Kn + k) * HWn + hw;
        g_aw[o] = z[k] * rs2;
        g_dy[o] = acc[18 + k] + sB[18 + k];
        g_dx[o] = acc[19 + k] + sB[19 + k];
    }
}

// ============================================================
// K3: split w_refer into bf16 hi/lo
// ============================================================
__global__ void k_wsplit(const float* __restrict__ w) {
    int i = blockIdx.x * 256 + threadIdx.x;
    float v = w[i];
    __nv_bfloat16 h = __float2bfloat16(v);
    g_wh[i] = h;
    g_wl[i] = __float2bfloat16(v - __bfloat162float(h));
}

// ============================================================
// K4: gather. Block = 32 pixels of one row (grid 128 x 8).
// Dedup'd taps padded to x8; tap loop unrolled x8 with 8
// independent accumulators (MLP 8). Outputs s as bf16 hi/lo.
// ============================================================
__global__ void __launch_bounds__(256)
k_gather() {
    __shared__ int   s_idx[32][48];
    __shared__ float s_w[32][48];
    __shared__ int   s_cnt[32];
    int yb  = blockIdx.x;            // 0..127
    int y   = yb >> 1;
    int x0  = (yb & 1) * 32;
    int b   = blockIdx.y;
    int tid = threadIdx.x;

    if (tid < 32) {
        int p = x0 + tid, hw = y*Wn + p;
        float gs = 0.f; int n = 0;
        #pragma unroll
        for (int k = 0; k < 9; k++) {
            int o = (b*Kn + k) * HWn + hw;
            float aw = g_aw[o];
            float dy = g_dy[o], dx = g_dx[o];
            float py = (float)y + dy;
            float px = (float)p + dx;
            float y0f = floorf(py), x0f = floorf(px);
            float wy = py - y0f, wx = px - x0f;
            int y0 = (int)y0f, xx0 = (int)x0f;
            float ws[4] = {(1.f-wy)*(1.f-wx), (1.f-wy)*wx, wy*(1.f-wx), wy*wx};
            int   yy[4] = {y0, y0, y0+1, y0+1};
            int   xx[4] = {xx0, xx0+1, xx0, xx0+1};
            #pragma unroll
            for (int t = 0; t < 4; t++) {
                bool v = (yy[t] >= 0) & (yy[t] < Hn) & (xx[t] >= 0) & (xx[t] < Wn);
                float w = ws[t] * aw;
                if (!v || w == 0.f) continue;
                int idx = (yy[t]*Wn + xx[t]) * Cn;
                gs += w;
                int j = 0;
                for (; j < n; j++)
                    if (s_idx[tid][j] == idx) { s_w[tid][j] += w; break; }
                if (j == n) { s_idx[tid][n] = idx; s_w[tid][n] = w; n++; }
            }
        }
        int n8 = (n + 7) & ~7;           // pad to multiple of 8 (<= 40)
        for (int j = n; j < n8; j++) { s_idx[tid][j] = 0; s_w[tid][j] = 0.f; }
        s_cnt[tid] = n8;
        g_g[b*HWn + hw] = gs;
    }
    __syncthreads();

    int c4 = tid & 63;          // float4 channel group
    int pg = tid >> 6;          // pixel phase (0..3)
    const float4* kb = (const float4*)(g_key_t + (size_t)b * HWn * Cn);
    #pragma unroll
    for (int it = 0; it < 8; it++) {
        int pl = pg + it*4;     // local pixel 0..31
        int n8 = s_cnt[pl];
        float4 a[8];
        #pragma unroll
        for (int u = 0; u < 8; u++) a[u] = make_float4(0.f, 0.f, 0.f, 0.f);

        for (int j = 0; j < n8; j += 8) {
            float w[8]; int ix[8];
            #pragma unroll
            for (int u = 0; u < 8; u++) { w[u] = s_w[pl][j+u]; ix[u] = s_idx[pl][j+u]; }
            float4 v[8];
            #pragma unroll
            for (int u = 0; u < 8; u++) v[u] = kb[(ix[u] >> 2) + c4];
            #pragma unroll
            for (int u = 0; u < 8; u++) {
                a[u].x += w[u]*v[u].x; a[u].y += w[u]*v[u].y;
                a[u].z += w[u]*v[u].z; a[u].w += w[u]*v[u].w;
            }
        }
        float4 acc;
        acc.x = ((a[0].x + a[1].x) + (a[2].x + a[3].x)) + ((a[4].x + a[5].x) + (a[6].x + a[7].x));
        acc.y = ((a[0].y + a[1].y) + (a[2].y + a[3].y)) + ((a[4].y + a[5].y) + (a[6].y + a[7].y));
        acc.z = ((a[0].z + a[1].z) + (a[2].z + a[3].z)) + ((a[4].z + a[5].z) + (a[6].z + a[7].z));
        acc.w = ((a[0].w + a[1].w) + (a[2].w + a[3].w)) + ((a[4].w + a[5].w) + (a[6].w + a[7].w));

        size_t base = ((size_t)(b*HWn + y*Wn + x0 + pl)) * Cn + c4*4;
        __nv_bfloat16 hx = __float2bfloat16(acc.x);
        __nv_bfloat16 hy = __float2bfloat16(acc.y);
        __nv_bfloat16 hz = __float2bfloat16(acc.z);
        __nv_bfloat16 hw4 = __float2bfloat16(acc.w);
        __nv_bfloat16 lx = __float2bfloat16(acc.x - __bfloat162float(hx));
        __nv_bfloat16 ly = __float2bfloat16(acc.y - __bfloat162float(hy));
        __nv_bfloat16 lz = __float2bfloat16(acc.z - __bfloat162float(hz));
        __nv_bfloat16 lw = __float2bfloat16(acc.w - __bfloat162float(hw4));
        __nv_bfloat162 h0 = __halves2bfloat162(hx, hy);
        __nv_bfloat162 h1 = __halves2bfloat162(hz, hw4);
        __nv_bfloat162 l0 = __halves2bfloat162(lx, ly);
        __nv_bfloat162 l1 = __halves2bfloat162(lz, lw);
        uint2 uh, ul;
        uh.x = *(uint32_t*)&h0; uh.y = *(uint32_t*)&h1;
        ul.x = *(uint32_t*)&l0; ul.y = *(uint32_t*)&l1;
        *(uint2*)&g_sh[base] = uh;
        *(uint2*)&g_sl[base] = ul;
    }
}

// ============================================================
// K5: mma.sync bf16 split GEMM with 3-stage cp.async pipeline
//   D[o,p] = Wh.Sh^T + Wl.Sh^T + Wh.Sl^T  (virtual K = 768)
// ============================================================
#define PITCH_B 80
#define TILE_B  (128*PITCH_B)
#define NCHUNK  24
#define GEMM_SMEM (3*2*TILE_B)

__global__ void __launch_bounds__(256)
k_gemm_mma(const float* __restrict__ bref, float* __restrict__ out) {
    extern __shared__ __align__(16) char gsmg[];
    int tid = threadIdx.x, wid = tid >> 5, lane = tid & 31;
    int p0 = blockIdx.x * 128;
    int o0 = blockIdx.y * 128;
    int bz = blockIdx.z;
    int wr = wid >> 2;
    int wn = wid & 3;

    const __nv_bfloat16* Aseg[3] = {g_wh, g_wl, g_wh};
    const __nv_bfloat16* Bseg[3] = {g_sh, g_sh, g_sl};
    uint32_t sbase = smem_u32(gsmg);

    int rA = tid >> 2;
    int pa = (tid & 3) * 16;

    float acc[4][4][4];
    #pragma unroll
    for (int i = 0; i < 4; i++)
        #pragma unroll
        for (int j = 0; j < 4; j++)
            #pragma unroll
            for (int r = 0; r < 4; r++) acc[i][j][r] = 0.f;

    int lm_row = ((lane >> 3) & 1) * 8 + (lane & 7);
    int lm_col = (lane >> 4) * 16;
    int bn_row = lane >> 2;
    int bn_col = (lane & 3) * 4;

#define ISSUE(CH) do { \
        int _st = (CH) % 3, _seg = (CH) >> 3, _c0 = ((CH) & 7) * 32; \
        const char* _Ag = (const char*)(Aseg[_seg] + (size_t)o0*Cn + _c0) \
                          + (size_t)rA*(Cn*2) + pa; \
        const char* _Bg = (const char*)(Bseg[_seg] + ((size_t)bz*HWn + p0)*Cn + _c0) \
                          + (size_t)rA*(Cn*2) + pa; \
        uint32_t _sa = sbase + _st*(2*TILE_B); \
        uint32_t _sb = _sa + TILE_B; \
        cp16(_sa + rA*PITCH_B + pa,        _Ag); \
        cp16(_sa + (rA+64)*PITCH_B + pa,   _Ag + 64*(Cn*2)); \
        cp16(_sb + rA*PITCH_B + pa,        _Bg); \
        cp16(_sb + (rA+64)*PITCH_B + pa,   _Bg + 64*(Cn*2)); \
        cp_commit(); \
    } while (0)

    ISSUE(0);
    ISSUE(1);

    for (int ch = 0; ch < NCHUNK; ch++) {
        if (ch == NCHUNK - 1) cp_wait<0>(); else cp_wait<1>();
        __syncthreads();
        if (ch + 2 < NCHUNK) ISSUE(ch + 2);

        uint32_t sa = sbase + (ch % 3)*(2*TILE_B);
        uint32_t sb = sa + TILE_B;
        #pragma unroll
        for (int ks = 0; ks < 2; ks++) {
            uint32_t bf[4][2];
            #pragma unroll
            for (int nt = 0; nt < 4; nt++) {
                uint32_t ba = sb + (wn*32 + nt*8 + bn_row)*PITCH_B + bn_col + ks*32;
                bf[nt][0] = lds32(ba);
                bf[nt][1] = lds32(ba + 16);
            }
            #pragma unroll
            for (int mt = 0; mt < 4; mt++) {
                uint32_t a0, a1, a2, a3;
                uint32_t aa = sa + (wr*64 + mt*16 + lm_row)*PITCH_B + lm_col + ks*32;
                ldmatrix_x4(a0, a1, a2, a3, aa);
                #pragma unroll
                for (int nt = 0; nt < 4; nt++)
                    mma16816(acc[mt][nt], a0, a1, a2, a3, bf[nt][0], bf[nt][1]);
            }
        }
    }
#undef ISSUE

    int mrow = lane >> 2;
    int ncol = (lane & 3) * 2;
    #pragma unroll
    for (int mt = 0; mt < 4; mt++) {
        int o = o0 + wr*64 + mt*16 + mrow;
        float bb0 = bref[o], bb1 = bref[o + 8];
        #pragma unroll
        for (int nt = 0; nt < 4; nt++) {
            int p = p0 + wn*32 + nt*8 + ncol;
            float2 gg = *(const float2*)&g_g[bz*HWn + p];
            float2 r0, r1;
            r0.x = acc[mt][nt][0] + bb0*gg.x;
            r0.y = acc[mt][nt][1] + bb0*gg.y;
            r1.x = acc[mt][nt][2] + bb1*gg.x;
            r1.y = acc[mt][nt][3] + bb1*gg.y;
            *(float2*)&out[((size_t)(bz*Cn + o))     * HWn + p] = r0;
            *(float2*)&out[((size_t)(bz*Cn + o + 8)) * HWn + p] = r1;
        }
    }
}

// ============================================================
extern "C" void kernel_launch(void* const* d_in, const int* in_sizes, int n_in,
                              void* d_out, int out_size) {
    const float* query   = (const float*)d_in[0];
    const float* key     = (const float*)d_in[1];
    const float* gmb     = (const float*)d_in[2];
    const float* w_refer = (const float*)d_in[3];
    const float* b_refer = (const float*)d_in[4];
    const float* w_attn  = (const float*)d_in[5];
    const float* b_attn  = (const float*)d_in[6];
    const float* w_mask  = (const float*)d_in[7];
    const float* b_mask  = (const float*)d_in[8];
    const float* w_off   = (const float*)d_in[9];
    const float* b_off   = (const float*)d_in[10];
    const unsigned* temp = (const unsigned*)d_in[11];
    float* out = (float*)d_out;

    static int attr_set = 0;
    if (!attr_set) {
        cudaFuncSetAttribute(k_gemm_mma, cudaFuncAttributeMaxDynamicSharedMemorySize,
                             GEMM_SMEM);
        attr_set = 1;
    }

    k_transpose<<<dim3(HWn/32, Cn/32, Bn), dim3(32, 8)>>>(key);
    k_params<<<NPIX/128, 256>>>(query, gmb, b_attn, b_mask, b_off,
                                w_attn, w_mask, w_off, temp);
    k_wsplit<<<Cn*Cn/256, 256>>>(w_refer);
    k_gather<<<dim3(2*Hn, Bn), 256>>>();
    k_gemm_mma<<<dim3(HWn/128, Cn/128, Bn), 256, GEMM_SMEM>>>(b_refer, out);
}

// round 10
// speedup vs baseline: 1.3029x; 1.3029x over previous
#include <cuda_runtime.h>
#include <cuda_bf16.h>
#include <cstdint>

#define Bn   8
#define Cn   256
#define Kn   9
#define Hn   64
#define Wn   64
#define HWn  (Hn*Wn)       // 4096
#define NPIX (Bn*HWn)      // 32768

// ---- scratch (device globals; no allocation allowed) ----
__device__ float g_key_t[(size_t)Bn*HWn*Cn];          // [B][HW][C] transposed key
__device__ __nv_bfloat16 g_sh[(size_t)NPIX*Cn];       // sampled features, bf16 hi
__device__ __nv_bfloat16 g_sl[(size_t)NPIX*Cn];       // sampled features, bf16 lo
__device__ __nv_bfloat16 g_wh[Cn*Cn];                 // w_refer hi
__device__ __nv_bfloat16 g_wl[Cn*Cn];                 // w_refer lo
__device__ float g_aw[Bn*Kn*HWn];
__device__ float g_dy[Bn*Kn*HWn];
__device__ float g_dx[Bn*Kn*HWn];
__device__ float g_g[NPIX];                            // bias weight-sum per pixel

// ================= helpers =================
__device__ __forceinline__ uint32_t smem_u32(const void* p) {
    uint32_t a;
    asm("{ .reg .u64 t; cvta.to.shared.u64 t, %1; cvt.u32.u64 %0, t; }" : "=r"(a) : "l"(p));
    return a;
}
__device__ __forceinline__ uint32_t lds32(uint32_t a) {
    uint32_t v;
    asm volatile("ld.shared.b32 %0, [%1];" : "=r"(v) : "r"(a));
    return v;
}
__device__ __forceinline__ void ldmatrix_x4(uint32_t& r0, uint32_t& r1,
                                            uint32_t& r2, uint32_t& r3, uint32_t a) {
    asm volatile("ldmatrix.sync.aligned.m8n8.x4.shared.b16 {%0,%1,%2,%3}, [%4];"
                 : "=r"(r0), "=r"(r1), "=r"(r2), "=r"(r3) : "r"(a));
}
__device__ __forceinline__ void mma16816(float* c, uint32_t a0, uint32_t a1,
                                         uint32_t a2, uint32_t a3,
                                         uint32_t b0, uint32_t b1) {
    asm volatile(
        "mma.sync.aligned.m16n8k16.row.col.f32.bf16.bf16.f32 "
        "{%0,%1,%2,%3}, {%4,%5,%6,%7}, {%8,%9}, {%0,%1,%2,%3};"
        : "+f"(c[0]), "+f"(c[1]), "+f"(c[2]), "+f"(c[3])
        : "r"(a0), "r"(a1), "r"(a2), "r"(a3), "r"(b0), "r"(b1));
}
__device__ __forceinline__ void cp16(uint32_t s, const void* g) {
    asm volatile("cp.async.cg.shared.global [%0], [%1], 16;" :: "r"(s), "l"(g));
}
__device__ __forceinline__ void cp_commit() {
    asm volatile("cp.async.commit_group;" ::: "memory");
}
template<int N> __device__ __forceinline__ void cp_wait() {
    asm volatile("cp.async.wait_group %0;" :: "n"(N) : "memory");
}

// ============================================================
// K1: transpose key_layer [B,C,HW] -> g_key_t [B,HW,C]
// ============================================================
__global__ void k_transpose(const float* __restrict__ key) {
    __shared__ float t[32][33];
    int b   = blockIdx.z;
    int hw0 = blockIdx.x * 32;
    int c0  = blockIdx.y * 32;
    int tx = threadIdx.x, ty = threadIdx.y;
    const float* src = key + (size_t)b * Cn * HWn;
    #pragma unroll
    for (int i = 0; i < 4; i++)
        t[ty + i*8][tx] = src[(size_t)(c0 + ty + i*8) * HWn + hw0 + tx];
    __syncthreads();
    float* dst = g_key_t + (size_t)b * HWn * Cn;
    #pragma unroll
    for (int i = 0; i < 4; i++)
        dst[(size_t)(hw0 + ty + i*8) * Cn + c0 + tx] = t[tx][ty + i*8];
}

// ============================================================
// K2: per-pixel params, split-C across two thread groups.
// ============================================================
__global__ void __launch_bounds__(256)
k_params(const float* __restrict__ query,
         const float* __restrict__ gmb,
         const float* __restrict__ b_attn,
         const float* __restrict__ b_mask,
         const float* __restrict__ b_off,
         const float* __restrict__ w_attn,
         const float* __restrict__ w_mask,
         const float* __restrict__ w_off,
         const unsigned* __restrict__ temp_raw) {
    __shared__ float4 sW[28*64];
    __shared__ float  sB[28];
    __shared__ float  sPart[128*29];
    int tid = threadIdx.x;
    for (int i = tid; i < 576; i += 256) sW[i]        = ((const float4*)w_attn)[i];
    for (int i = tid; i < 576; i += 256) sW[576 + i]  = ((const float4*)w_mask)[i];
    for (int i = tid; i < 640; i += 256) sW[1152 + i] = ((const float4*)w_off)[i];
    if (tid < 9)  { sB[tid] = b_attn[tid]; sB[9 + tid] = b_mask[tid]; }
    if (tid < 10) sB[18 + tid] = b_off[tid];
    __syncthreads();

    int lp = tid & 127, ph = tid >> 7;
    int pix = blockIdx.x * 128 + lp;
    int b  = pix >> 12;
    int hw = pix & (HWn - 1);

    const float* q = query + (size_t)b * Cn * HWn + (size_t)(ph*128) * HWn + hw;
    float acc[28];
    #pragma unroll
    for (int r = 0; r < 28; r++) acc[r] = 0.f;

    #pragma unroll 4
    for (int c4 = 0; c4 < 32; c4++) {
        float q0 = q[(c4*4 + 0) * HWn];
        float q1 = q[(c4*4 + 1) * HWn];
        float q2 = q[(c4*4 + 2) * HWn];
        float q3 = q[(c4*4 + 3) * HWn];
        #pragma unroll
        for (int r = 0; r < 28; r++) {
            float4 w = sW[r*64 + ph*32 + c4];
            acc[r] += q0*w.x + q1*w.y + q2*w.z + q3*w.w;
        }
    }

    if (ph == 1) {
        #pragma unroll
        for (int r = 0; r < 28; r++) sPart[lp*29 + r] = acc[r];
    }
    __syncthreads();
    if (ph == 1) return;

    #pragma unroll
    for (int r = 0; r < 28; r++) acc[r] += sPart[lp*29 + r];

    unsigned lo = temp_raw[0];
    float t;
    if      (lo == 1u)           t = 1.f;
    else if (lo == 0x3F800000u)  t = 1.f;
    else if (lo == 0u)           t = 1.f;
    else                         t = __uint_as_float(lo);
    float invt = 1.f / t;

    float mv[9]; float mx = -3.4e38f;
    #pragma unroll
    for (int k = 0; k < 9; k++) {
        float gk = gmb[(size_t)(b*Kn + k) * HWn + hw];
        mv[k] = (acc[9 + k] + sB[9 + k] + gk) * invt;
        mx = fmaxf(mx, mv[k]);
    }
    float sum = 0.f;
    #pragma unroll
    for (int k = 0; k < 9; k++) { mv[k] = expf(mv[k] - mx); sum += mv[k]; }
    float rs = 1.f / sum;

    float z[9]; float mx2 = -3.4e38f;
    #pragma unroll
    for (int k = 0; k < 9; k++) {
        z[k] = (acc[k] + sB[k]) * (mv[k] * rs);
        mx2 = fmaxf(mx2, z[k]);
    }
    float sum2 = 0.f;
    #pragma unroll
    for (int k = 0; k < 9; k++) { z[k] = expf(z[k] - mx2); sum2 += z[k]; }
    float rs2 = 1.f / sum2;

    #pragma unroll
    for (int k = 0; k < 9; k++) {
        int o = (b*Kn + k) * HWn + hw;
        g_aw[o] = z[k] * rs2;
        g_dy[o] = acc[18 + k] + sB[18 + k];
        g_dx[o] = acc[19 + k] + sB[19 + k];
    }
}

// ============================================================
// K3: split w_refer into bf16 hi/lo
// ============================================================
__global__ void k_wsplit(const float* __restrict__ w) {
    int i = blockIdx.x * 256 + threadIdx.x;
    float v = w[i];
    __nv_bfloat16 h = __float2bfloat16(v);
    g_wh[i] = h;
    g_wl[i] = __float2bfloat16(v - __bfloat162float(h));
}

// ============================================================
// K4: STENCIL gather. Block = (row y, batch b, channel-half cq).
// Phase 0 (warps 0-1): fold 36 bilinear corner weights into a
//   dense per-pixel 3x3 stencil (+tiny overflow list for far taps).
// Phase 0' (warps 2-7, concurrent): stage 3-row x 64-px x 128-ch
//   window into SMEM.
// Phase 1: all threads, 9 conflict-free LDS.128 per item.
// ============================================================
#define CHQ 128                           // channels per block (half)
#define OVC 16                            // overflow cap per pixel
// smem layout (bytes):
//   win   @0        : 3*64*CHQ*4 = 98304
//   w9    @98304    : 64*9*4     = 2304
//   ovf_w @100608   : 64*OVC*4   = 4096
//   ovf_i @104704   : 64*OVC*4   = 4096
//   novf  @108800   : 64*4       = 256
#define GATHER_SMEM 109056

__global__ void __launch_bounds__(256)
k_gather() {
    extern __shared__ __align__(16) char gsm[];
    float4* win4  = (float4*)gsm;
    float*  w9s   = (float*)(gsm + 98304);
    float*  ovf_w = (float*)(gsm + 100608);
    int*    ovf_i = (int*)(gsm + 104704);
    int*    novf  = (int*)(gsm + 108800);

    int y   = blockIdx.x;
    int b   = blockIdx.y;
    int cq  = blockIdx.z;        // 0/1 channel half
    int tid = threadIdx.x;
    const float4* kb4 = (const float4*)(g_key_t + (size_t)b * HWn * Cn);

    if (tid < 64) {
        // ---- stencil build: one thread per pixel ----
        int p = tid, hw = y*Wn + p;
        float w9[9];
        #pragma unroll
        for (int i = 0; i < 9; i++) w9[i] = 0.f;
        float gs = 0.f; int cnt = 0;
        #pragma unroll
        for (int k = 0; k < 9; k++) {
            int o = (b*Kn + k) * HWn + hw;
            float aw = g_aw[o];
            float dy = g_dy[o], dx = g_dx[o];
            float py = (float)y + dy;
            float px = (float)p + dx;
            float y0f = floorf(py), x0f = floorf(px);
            float wy = py - y0f, wx = px - x0f;
            int y0 = (int)y0f, x0 = (int)x0f;
            float ws[4] = {(1.f-wy)*(1.f-wx), (1.f-wy)*wx, wy*(1.f-wx), wy*wx};
            int   yy[4] = {y0, y0, y0+1, y0+1};
            int   xx[4] = {x0, x0+1, x0, x0+1};
            #pragma unroll
            for (int t = 0; t < 4; t++) {
                bool v = (yy[t] >= 0) & (yy[t] < Hn) & (xx[t] >= 0) & (xx[t] < Wn);
                float w = ws[t] * aw;
                if (!v || w == 0.f) continue;
                gs += w;
                int sy = yy[t] - (y - 1);
                int sx = xx[t] - (p - 1);
                if (sy >= 0 && sy < 3 && sx >= 0 && sx < 3) {
                    w9[sy*3 + sx] += w;
                } else if (cnt < OVC) {
                    ovf_w[p*OVC + cnt] = w;
                    ovf_i[p*OVC + cnt] = yy[t]*Wn + xx[t];
                    cnt++;
                }
            }
        }
        #pragma unroll
        for (int i = 0; i < 9; i++) w9s[p*9 + i] = w9[i];
        novf[p] = cnt;
        if (cq == 0) g_g[b*HWn + hw] = gs;
    } else {
        // ---- window staging: warps 2-7 ----
        int t = tid - 64;
        float4 z4 = make_float4(0.f, 0.f, 0.f, 0.f);
        #pragma unroll
        for (int it = 0; it < 32; it++) {
            int i = t + it*192;          // 0 .. 6143
            int r   = i >> 11;           // window row 0..2
            int rem = i & 2047;          // x*32 + g
            int ry = y - 1 + r;
            float4 v = z4;
            if (ry >= 0 && ry < Hn)
                v = kb4[((size_t)(ry*Wn) << 6) + ((rem >> 5) << 6) + cq*32 + (rem & 31)];
            win4[i] = v;
        }
    }
    __syncthreads();

    // ---- compute: 32 c4-groups x 64 pixels = 2048 items, 8/thread ----
    int c4 = tid & 31;           // float4 group within 128-ch half
    int pg = tid >> 5;           // warp id = pixel phase
    #pragma unroll
    for (int it = 0; it < 8; it++) {
        int p = pg*8 + it;
        int cm1 = max(p - 1, 0), cp1 = min(p + 1, Wn - 1);
        int col32[3] = {cm1*32, p*32, cp1*32};
        float w9[9];
        #pragma unroll
        for (int i = 0; i < 9; i++) w9[i] = w9s[p*9 + i];

        float4 acc = make_float4(0.f, 0.f, 0.f, 0.f);
        #pragma unroll
        for (int k = 0; k < 9; k++) {
            float w = w9[k];
            float4 v = win4[(k/3)*2048 + col32[k%3] + c4];
            acc.x += w*v.x; acc.y += w*v.y; acc.z += w*v.z; acc.w += w*v.w;
        }
        int nov = novf[p];
        for (int j = 0; j < nov; j++) {
            float w  = ovf_w[p*OVC + j];
            int   hwt = ovf_i[p*OVC + j];
            float4 v = kb4[hwt*64 + cq*32 + c4];
            acc.x += w*v.x; acc.y += w*v.y; acc.z += w*v.z; acc.w += w*v.w;
        }

        size_t base = ((size_t)(b*HWn + y*Wn + p)) * Cn + cq*CHQ + c4*4;
        __nv_bfloat16 hx = __float2bfloat16(acc.x);
        __nv_bfloat16 hy = __float2bfloat16(acc.y);
        __nv_bfloat16 hz = __float2bfloat16(acc.z);
        __nv_bfloat16 hw4 = __float2bfloat16(acc.w);
        __nv_bfloat16 lx = __float2bfloat16(acc.x - __bfloat162float(hx));
        __nv_bfloat16 ly = __float2bfloat16(acc.y - __bfloat162float(hy));
        __nv_bfloat16 lz = __float2bfloat16(acc.z - __bfloat162float(hz));
        __nv_bfloat16 lw = __float2bfloat16(acc.w - __bfloat162float(hw4));
        __nv_bfloat162 h0 = __halves2bfloat162(hx, hy);
        __nv_bfloat162 h1 = __halves2bfloat162(hz, hw4);
        __nv_bfloat162 l0 = __halves2bfloat162(lx, ly);
        __nv_bfloat162 l1 = __halves2bfloat162(lz, lw);
        uint2 uh, ul;
        uh.x = *(uint32_t*)&h0; uh.y = *(uint32_t*)&h1;
        ul.x = *(uint32_t*)&l0; ul.y = *(uint32_t*)&l1;
        *(uint2*)&g_sh[base] = uh;
        *(uint2*)&g_sl[base] = ul;
    }
}

// ============================================================
// K5: mma.sync bf16 split GEMM with 3-stage cp.async pipeline
//   D[o,p] = Wh.Sh^T + Wl.Sh^T + Wh.Sl^T  (virtual K = 768)
// ============================================================
#define PITCH_B 80
#define TILE_B  (128*PITCH_B)
#define NCHUNK  24
#define GEMM_SMEM (3*2*TILE_B)

__global__ void __launch_bounds__(256)
k_gemm_mma(const float* __restrict__ bref, float* __restrict__ out) {
    extern __shared__ __align__(16) char gsmg[];
    int tid = threadIdx.x, wid = tid >> 5, lane = tid & 31;
    int p0 = blockIdx.x * 128;
    int o0 = blockIdx.y * 128;
    int bz = blockIdx.z;
    int wr = wid >> 2;
    int wn = wid & 3;

    const __nv_bfloat16* Aseg[3] = {g_wh, g_wl, g_wh};
    const __nv_bfloat16* Bseg[3] = {g_sh, g_sh, g_sl};
    uint32_t sbase = smem_u32(gsmg);

    int rA = tid >> 2;
    int pa = (tid & 3) * 16;

    float acc[4][4][4];
    #pragma unroll
    for (int i = 0; i < 4; i++)
        #pragma unroll
        for (int j = 0; j < 4; j++)
            #pragma unroll
            for (int r = 0; r < 4; r++) acc[i][j][r] = 0.f;

    int lm_row = ((lane >> 3) & 1) * 8 + (lane & 7);
    int lm_col = (lane >> 4) * 16;
    int bn_row = lane >> 2;
    int bn_col = (lane & 3) * 4;

#define ISSUE(CH) do { \
        int _st = (CH) % 3, _seg = (CH) >> 3, _c0 = ((CH) & 7) * 32; \
        const char* _Ag = (const char*)(Aseg[_seg] + (size_t)o0*Cn + _c0) \
                          + (size_t)rA*(Cn*2) + pa; \
        const char* _Bg = (const char*)(Bseg[_seg] + ((size_t)bz*HWn + p0)*Cn + _c0) \
                          + (size_t)rA*(Cn*2) + pa; \
        uint32_t _sa = sbase + _st*(2*TILE_B); \
        uint32_t _sb = _sa + TILE_B; \
        cp16(_sa + rA*PITCH_B + pa,        _Ag); \
        cp16(_sa + (rA+64)*PITCH_B + pa,   _Ag + 64*(Cn*2)); \
        cp16(_sb + rA*PITCH_B + pa,        _Bg); \
        cp16(_sb + (rA+64)*PITCH_B + pa,   _Bg + 64*(Cn*2)); \
        cp_commit(); \
    } while (0)

    ISSUE(0);
    ISSUE(1);

    for (int ch = 0; ch < NCHUNK; ch++) {
        if (ch == NCHUNK - 1) cp_wait<0>(); else cp_wait<1>();
        __syncthreads();
        if (ch + 2 < NCHUNK) ISSUE(ch + 2);

        uint32_t sa = sbase + (ch % 3)*(2*TILE_B);
        uint32_t sb = sa + TILE_B;
        #pragma unroll
        for (int ks = 0; ks < 2; ks++) {
            uint32_t bf[4][2];
            #pragma unroll
            for (int nt = 0; nt < 4; nt++) {
                uint32_t ba = sb + (wn*32 + nt*8 + bn_row)*PITCH_B + bn_col + ks*32;
                bf[nt][0] = lds32(ba);
                bf[nt][1] = lds32(ba + 16);
            }
            #pragma unroll
            for (int mt = 0; mt < 4; mt++) {
                uint32_t a0, a1, a2, a3;
                uint32_t aa = sa + (wr*64 + mt*16 + lm_row)*PITCH_B + lm_col + ks*32;
                ldmatrix_x4(a0, a1, a2, a3, aa);
                #pragma unroll
                for (int nt = 0; nt < 4; nt++)
                    mma16816(acc[mt][nt], a0, a1, a2, a3, bf[nt][0], bf[nt][1]);
            }
        }
    }
#undef ISSUE

    int mrow = lane >> 2;
    int ncol = (lane & 3) * 2;
    #pragma unroll
    for (int mt = 0; mt < 4; mt++) {
        int o = o0 + wr*64 + mt*16 + mrow;
        float bb0 = bref[o], bb1 = bref[o + 8];
        #pragma unroll
        for (int nt = 0; nt < 4; nt++) {
            int p = p0 + wn*32 + nt*8 + ncol;
            float2 gg = *(const float2*)&g_g[bz*HWn + p];
            float2 r0, r1;
            r0.x = acc[mt][nt][0] + bb0*gg.x;
            r0.y = acc[mt][nt][1] + bb0*gg.y;
            r1.x = acc[mt][nt][2] + bb1*gg.x;
            r1.y = acc[mt][nt][3] + bb1*gg.y;
            *(float2*)&out[((size_t)(bz*Cn + o))     * HWn + p] = r0;
            *(float2*)&out[((size_t)(bz*Cn + o + 8)) * HWn + p] = r1;
        }
    }
}

// ============================================================
extern "C" void kernel_launch(void* const* d_in, const int* in_sizes, int n_in,
                              void* d_out, int out_size) {
    const float* query   = (const float*)d_in[0];
    const float* key     = (const float*)d_in[1];
    const float* gmb     = (const float*)d_in[2];
    const float* w_refer = (const float*)d_in[3];
    const float* b_refer = (const float*)d_in[4];
    const float* w_attn  = (const float*)d_in[5];
    const float* b_attn  = (const float*)d_in[6];
    const float* w_mask  = (const float*)d_in[7];
    const float* b_mask  = (const float*)d_in[8];
    const float* w_off   = (const float*)d_in[9];
    const float* b_off   = (const float*)d_in[10];
    const unsigned* temp = (const unsigned*)d_in[11];
    float* out = (float*)d_out;

    static int attr_set = 0;
    if (!attr_set) {
        cudaFuncSetAttribute(k_gemm_mma, cudaFuncAttributeMaxDynamicSharedMemorySize,
                             GEMM_SMEM);
        cudaFuncSetAttribute(k_gather, cudaFuncAttributeMaxDynamicSharedMemorySize,
                             GATHER_SMEM);
        attr_set = 1;
    }

    k_transpose<<<dim3(HWn/32, Cn/32, Bn), dim3(32, 8)>>>(key);
    k_params<<<NPIX/128, 256>>>(query, gmb, b_attn, b_mask, b_off,
                                w_attn, w_mask, w_off, temp);
    k_wsplit<<<Cn*Cn/256, 256>>>(w_refer);
    k_gather<<<dim3(Hn, Bn, 2), 256, GATHER_SMEM>>>();
    k_gemm_mma<<<dim3(HWn/128, Cn/128, Bn), 256, GEMM_SMEM>>>(b_refer, out);
}

// round 11
// speedup vs baseline: 1.3361x; 1.0256x over previous
#include <cuda_runtime.h>
#include <cuda_bf16.h>
#include <cstdint>

#define Bn   8
#define Cn   256
#define Kn   9
#define Hn   64
#define Wn   64
#define HWn  (Hn*Wn)       // 4096
#define NPIX (Bn*HWn)      // 32768
#define OVC  8             // overflow taps per pixel (far taps, rare)

// ---- scratch (device globals; no allocation allowed) ----
__device__ float g_key_t[(size_t)Bn*HWn*Cn];          // [B][HW][C] transposed key
__device__ __nv_bfloat16 g_sh[(size_t)NPIX*Cn];       // sampled features, bf16 hi
__device__ __nv_bfloat16 g_sl[(size_t)NPIX*Cn];       // sampled features, bf16 lo
__device__ __nv_bfloat16 g_wh[Cn*Cn];                 // w_refer hi
__device__ __nv_bfloat16 g_wl[Cn*Cn];                 // w_refer lo
__device__ float g_w9[9*NPIX];                         // dense 3x3 stencil [j][pix]
__device__ float g_ovw[NPIX*OVC];                      // overflow weights
__device__ int   g_ovi[NPIX*OVC];                      // overflow hw idx
__device__ int   g_ovn[NPIX];                          // overflow counts
__device__ float g_g[NPIX];                            // bias weight-sum per pixel

// ================= helpers =================
__device__ __forceinline__ uint32_t smem_u32(const void* p) {
    uint32_t a;
    asm("{ .reg .u64 t; cvta.to.shared.u64 t, %1; cvt.u32.u64 %0, t; }" : "=r"(a) : "l"(p));
    return a;
}
__device__ __forceinline__ uint32_t lds32(uint32_t a) {
    uint32_t v;
    asm volatile("ld.shared.b32 %0, [%1];" : "=r"(v) : "r"(a));
    return v;
}
__device__ __forceinline__ void ldmatrix_x4(uint32_t& r0, uint32_t& r1,
                                            uint32_t& r2, uint32_t& r3, uint32_t a) {
    asm volatile("ldmatrix.sync.aligned.m8n8.x4.shared.b16 {%0,%1,%2,%3}, [%4];"
                 : "=r"(r0), "=r"(r1), "=r"(r2), "=r"(r3) : "r"(a));
}
__device__ __forceinline__ void mma16816(float* c, uint32_t a0, uint32_t a1,
                                         uint32_t a2, uint32_t a3,
                                         uint32_t b0, uint32_t b1) {
    asm volatile(
        "mma.sync.aligned.m16n8k16.row.col.f32.bf16.bf16.f32 "
        "{%0,%1,%2,%3}, {%4,%5,%6,%7}, {%8,%9}, {%0,%1,%2,%3};"
        : "+f"(c[0]), "+f"(c[1]), "+f"(c[2]), "+f"(c[3])
        : "r"(a0), "r"(a1), "r"(a2), "r"(a3), "r"(b0), "r"(b1));
}
__device__ __forceinline__ void cp16(uint32_t s, const void* g) {
    asm volatile("cp.async.cg.shared.global [%0], [%1], 16;" :: "r"(s), "l"(g));
}
__device__ __forceinline__ void cp_commit() {
    asm volatile("cp.async.commit_group;" ::: "memory");
}
template<int N> __device__ __forceinline__ void cp_wait() {
    asm volatile("cp.async.wait_group %0;" :: "n"(N) : "memory");
}

// ============================================================
// K1: transpose key_layer [B,C,HW] -> g_key_t [B,HW,C]
// ============================================================
__global__ void k_transpose(const float* __restrict__ key) {
    __shared__ float t[32][33];
    int b   = blockIdx.z;
    int hw0 = blockIdx.x * 32;
    int c0  = blockIdx.y * 32;
    int tx = threadIdx.x, ty = threadIdx.y;
    const float* src = key + (size_t)b * Cn * HWn;
    #pragma unroll
    for (int i = 0; i < 4; i++)
        t[ty + i*8][tx] = src[(size_t)(c0 + ty + i*8) * HWn + hw0 + tx];
    __syncthreads();
    float* dst = g_key_t + (size_t)b * HWn * Cn;
    #pragma unroll
    for (int i = 0; i < 4; i++)
        dst[(size_t)(hw0 + ty + i*8) * Cn + c0 + tx] = t[tx][ty + i*8];
}

// ============================================================
// K2: per-pixel params + softmaxes + DENSE 3x3 stencil fold.
// Block = 128 pixels, 256 threads, split-C reduction.
// ============================================================
__global__ void __launch_bounds__(256)
k_params(const float* __restrict__ query,
         const float* __restrict__ gmb,
         const float* __restrict__ b_attn,
         const float* __restrict__ b_mask,
         const float* __restrict__ b_off,
         const float* __restrict__ w_attn,
         const float* __restrict__ w_mask,
         const float* __restrict__ w_off,
         const unsigned* __restrict__ temp_raw) {
    __shared__ float4 sW[28*64];
    __shared__ float  sB[28];
    __shared__ float  sPart[128*29];
    int tid = threadIdx.x;
    for (int i = tid; i < 576; i += 256) sW[i]        = ((const float4*)w_attn)[i];
    for (int i = tid; i < 576; i += 256) sW[576 + i]  = ((const float4*)w_mask)[i];
    for (int i = tid; i < 640; i += 256) sW[1152 + i] = ((const float4*)w_off)[i];
    if (tid < 9)  { sB[tid] = b_attn[tid]; sB[9 + tid] = b_mask[tid]; }
    if (tid < 10) sB[18 + tid] = b_off[tid];
    __syncthreads();

    int lp = tid & 127, ph = tid >> 7;
    int pix = blockIdx.x * 128 + lp;
    int b  = pix >> 12;
    int hw = pix & (HWn - 1);

    const float* q = query + (size_t)b * Cn * HWn + (size_t)(ph*128) * HWn + hw;
    float acc[28];
    #pragma unroll
    for (int r = 0; r < 28; r++) acc[r] = 0.f;

    #pragma unroll 4
    for (int c4 = 0; c4 < 32; c4++) {
        float q0 = q[(c4*4 + 0) * HWn];
        float q1 = q[(c4*4 + 1) * HWn];
        float q2 = q[(c4*4 + 2) * HWn];
        float q3 = q[(c4*4 + 3) * HWn];
        #pragma unroll
        for (int r = 0; r < 28; r++) {
            float4 w = sW[r*64 + ph*32 + c4];
            acc[r] += q0*w.x + q1*w.y + q2*w.z + q3*w.w;
        }
    }

    if (ph == 1) {
        #pragma unroll
        for (int r = 0; r < 28; r++) sPart[lp*29 + r] = acc[r];
    }
    __syncthreads();
    if (ph == 1) return;

    #pragma unroll
    for (int r = 0; r < 28; r++) acc[r] += sPart[lp*29 + r];

    unsigned lo = temp_raw[0];
    float t;
    if      (lo == 1u)           t = 1.f;
    else if (lo == 0x3F800000u)  t = 1.f;
    else if (lo == 0u)           t = 1.f;
    else                         t = __uint_as_float(lo);
    float invt = 1.f / t;

    float mv[9]; float mx = -3.4e38f;
    #pragma unroll
    for (int k = 0; k < 9; k++) {
        float gk = gmb[(size_t)(b*Kn + k) * HWn + hw];
        mv[k] = (acc[9 + k] + sB[9 + k] + gk) * invt;
        mx = fmaxf(mx, mv[k]);
    }
    float sum = 0.f;
    #pragma unroll
    for (int k = 0; k < 9; k++) { mv[k] = expf(mv[k] - mx); sum += mv[k]; }
    float rs = 1.f / sum;

    float z[9]; float mx2 = -3.4e38f;
    #pragma unroll
    for (int k = 0; k < 9; k++) {
        z[k] = (acc[k] + sB[k]) * (mv[k] * rs);
        mx2 = fmaxf(mx2, z[k]);
    }
    float sum2 = 0.f;
    #pragma unroll
    for (int k = 0; k < 9; k++) { z[k] = expf(z[k] - mx2); sum2 += z[k]; }
    float rs2 = 1.f / sum2;

    // ---- dense 3x3 stencil fold (registers, predicated adds) ----
    int py0 = hw >> 6, px0 = hw & 63;
    float w9[9];
    #pragma unroll
    for (int i = 0; i < 9; i++) w9[i] = 0.f;
    float gs = 0.f; int cnt = 0;

    #pragma unroll
    for (int k = 0; k < 9; k++) {
        float aw = z[k] * rs2;
        float dy = acc[18 + k] + sB[18 + k];
        float dx = acc[19 + k] + sB[19 + k];
        float py = (float)py0 + dy;
        float px = (float)px0 + dx;
        float y0f = floorf(py), x0f = floorf(px);
        float wy = py - y0f, wx = px - x0f;
        int y0 = (int)y0f, x0 = (int)x0f;
        float ws[4] = {(1.f-wy)*(1.f-wx), (1.f-wy)*wx, wy*(1.f-wx), wy*wx};
        int   yy[4] = {y0, y0, y0+1, y0+1};
        int   xx[4] = {x0, x0+1, x0, x0+1};
        #pragma unroll
        for (int t4 = 0; t4 < 4; t4++) {
            bool v = (yy[t4] >= 0) & (yy[t4] < Hn) & (xx[t4] >= 0) & (xx[t4] < Wn);
            float w = ws[t4] * aw;
            if (!v || w == 0.f) continue;
            gs += w;
            int sy = yy[t4] - (py0 - 1);
            int sx = xx[t4] - (px0 - 1);
            if (sy >= 0 && sy < 3 && sx >= 0 && sx < 3) {
                int s9 = sy*3 + sx;
                #pragma unroll
                for (int s = 0; s < 9; s++)
                    w9[s] += (s9 == s) ? w : 0.f;
            } else if (cnt < OVC) {
                g_ovw[pix*OVC + cnt] = w;
                g_ovi[pix*OVC + cnt] = yy[t4]*Wn + xx[t4];
                cnt++;
            }
        }
    }
    g_ovn[pix] = cnt;
    g_g[pix]   = gs;
    #pragma unroll
    for (int j = 0; j < 9; j++) g_w9[j*NPIX + pix] = w9[j];
}

// ============================================================
// K3: split w_refer into bf16 hi/lo
// ============================================================
__global__ void k_wsplit(const float* __restrict__ w) {
    int i = blockIdx.x * 256 + threadIdx.x;
    float v = w[i];
    __nv_bfloat16 h = __float2bfloat16(v);
    g_wh[i] = h;
    g_wl[i] = __float2bfloat16(v - __bfloat162float(h));
}

// ============================================================
// K4: STENCIL gather. Block = (row y, batch b, channel-quarter cq).
// Loads precomputed stencil, stages 3x64x64ch window (48KB) with
// all 256 threads, computes via conflict-free LDS.128. 4 CTAs/SM.
// ============================================================
// smem: win4 @0 : 3*64*16 float4 = 49152 B
//       w9s  @49152 : 576*4 = 2304 B
//       nov  @51456 : 64*4  = 256 B
#define GATHER_SMEM 51712

__global__ void __launch_bounds__(256, 4)
k_gather() {
    extern __shared__ __align__(16) char gsm[];
    float4* win4 = (float4*)gsm;
    float*  w9s  = (float*)(gsm + 49152);
    int*    nov  = (int*)(gsm + 51456);

    int y   = blockIdx.x;
    int b   = blockIdx.y;
    int cq  = blockIdx.z;        // 0..3 channel quarter
    int tid = threadIdx.x;
    int pixbase = b*HWn + y*Wn;
    const float4* kb4 = (const float4*)(g_key_t + (size_t)b * HWn * Cn);

    // load stencils (coalesced over pix)
    for (int i = tid; i < 576; i += 256) {
        int p = i / 9, j = i - p*9;
        w9s[i] = g_w9[j*NPIX + pixbase + p];
    }
    if (tid < 64) nov[tid] = g_ovn[pixbase + tid];

    // stage window: 3 rows x 64 px x 16 float4
    float4 z4 = make_float4(0.f, 0.f, 0.f, 0.f);
    #pragma unroll
    for (int it = 0; it < 12; it++) {
        int i   = tid + it*256;      // 0..3071
        int r   = i >> 10;
        int rem = i & 1023;          // x*16 + c
        int ry  = y - 1 + r;
        float4 v = z4;
        if (ry >= 0 && ry < Hn)
            v = kb4[((size_t)(ry*Wn) << 6) + ((rem >> 4) << 6) + cq*16 + (rem & 15)];
        win4[i] = v;
    }
    __syncthreads();

    // compute: 16 c4-groups x 64 pixels = 1024 items, 4/thread
    int c4 = tid & 15;
    #pragma unroll
    for (int it = 0; it < 4; it++) {
        int p = (tid >> 4) + it*16;
        int cm1 = max(p - 1, 0), cp1 = min(p + 1, Wn - 1);
        int col16[3] = {cm1*16, p*16, cp1*16};
        float w9[9];
        #pragma unroll
        for (int i = 0; i < 9; i++) w9[i] = w9s[p*9 + i];

        float4 acc = make_float4(0.f, 0.f, 0.f, 0.f);
        #pragma unroll
        for (int k = 0; k < 9; k++) {
            float w = w9[k];
            float4 v = win4[(k/3)*1024 + col16[k%3] + c4];
            acc.x += w*v.x; acc.y += w*v.y; acc.z += w*v.z; acc.w += w*v.w;
        }
        int nv = nov[p];
        for (int j = 0; j < nv; j++) {
            int pix = pixbase + p;
            float w   = g_ovw[pix*OVC + j];
            int   hwt = g_ovi[pix*OVC + j];
            float4 v = kb4[hwt*64 + cq*16 + c4];
            acc.x += w*v.x; acc.y += w*v.y; acc.z += w*v.z; acc.w += w*v.w;
        }

        size_t base = ((size_t)(pixbase + p)) * Cn + cq*64 + c4*4;
        __nv_bfloat16 hx = __float2bfloat16(acc.x);
        __nv_bfloat16 hy = __float2bfloat16(acc.y);
        __nv_bfloat16 hz = __float2bfloat16(acc.z);
        __nv_bfloat16 hw4 = __float2bfloat16(acc.w);
        __nv_bfloat16 lx = __float2bfloat16(acc.x - __bfloat162float(hx));
        __nv_bfloat16 ly = __float2bfloat16(acc.y - __bfloat162float(hy));
        __nv_bfloat16 lz = __float2bfloat16(acc.z - __bfloat162float(hz));
        __nv_bfloat16 lw = __float2bfloat16(acc.w - __bfloat162float(hw4));
        __nv_bfloat162 h0 = __halves2bfloat162(hx, hy);
        __nv_bfloat162 h1 = __halves2bfloat162(hz, hw4);
        __nv_bfloat162 l0 = __halves2bfloat162(lx, ly);
        __nv_bfloat162 l1 = __halves2bfloat162(lz, lw);
        uint2 uh, ul;
        uh.x = *(uint32_t*)&h0; uh.y = *(uint32_t*)&h1;
        ul.x = *(uint32_t*)&l0; ul.y = *(uint32_t*)&l1;
        *(uint2*)&g_sh[base] = uh;
        *(uint2*)&g_sl[base] = ul;
    }
}

// ============================================================
// K5: mma.sync bf16 split GEMM with 3-stage cp.async pipeline
//   D[o,p] = Wh.Sh^T + Wl.Sh^T + Wh.Sl^T  (virtual K = 768)
// ============================================================
#define PITCH_B 80
#define TILE_B  (128*PITCH_B)
#define NCHUNK  24
#define GEMM_SMEM (3*2*TILE_B)

__global__ void __launch_bounds__(256)
k_gemm_mma(const float* __restrict__ bref, float* __restrict__ out) {
    extern __shared__ __align__(16) char gsmg[];
    int tid = threadIdx.x, wid = tid >> 5, lane = tid & 31;
    int p0 = blockIdx.x * 128;
    int o0 = blockIdx.y * 128;
    int bz = blockIdx.z;
    int wr = wid >> 2;
    int wn = wid & 3;

    const __nv_bfloat16* Aseg[3] = {g_wh, g_wl, g_wh};
    const __nv_bfloat16* Bseg[3] = {g_sh, g_sh, g_sl};
    uint32_t sbase = smem_u32(gsmg);

    int rA = tid >> 2;
    int pa = (tid & 3) * 16;

    float acc[4][4][4];
    #pragma unroll
    for (int i = 0; i < 4; i++)
        #pragma unroll
        for (int j = 0; j < 4; j++)
            #pragma unroll
            for (int r = 0; r < 4; r++) acc[i][j][r] = 0.f;

    int lm_row = ((lane >> 3) & 1) * 8 + (lane & 7);
    int lm_col = (lane >> 4) * 16;
    int bn_row = lane >> 2;
    int bn_col = (lane & 3) * 4;

#define ISSUE(CH) do { \
        int _st = (CH) % 3, _seg = (CH) >> 3, _c0 = ((CH) & 7) * 32; \
        const char* _Ag = (const char*)(Aseg[_seg] + (size_t)o0*Cn + _c0) \
                          + (size_t)rA*(Cn*2) + pa; \
        const char* _Bg = (const char*)(Bseg[_seg] + ((size_t)bz*HWn + p0)*Cn + _c0) \
                          + (size_t)rA*(Cn*2) + pa; \
        uint32_t _sa = sbase + _st*(2*TILE_B); \
        uint32_t _sb = _sa + TILE_B; \
        cp16(_sa + rA*PITCH_B + pa,        _Ag); \
        cp16(_sa + (rA+64)*PITCH_B + pa,   _Ag + 64*(Cn*2)); \
        cp16(_sb + rA*PITCH_B + pa,        _Bg); \
        cp16(_sb + (rA+64)*PITCH_B + pa,   _Bg + 64*(Cn*2)); \
        cp_commit(); \
    } while (0)

    ISSUE(0);
    ISSUE(1);

    for (int ch = 0; ch < NCHUNK; ch++) {
        if (ch == NCHUNK - 1) cp_wait<0>(); else cp_wait<1>();
        __syncthreads();
        if (ch + 2 < NCHUNK) ISSUE(ch + 2);

        uint32_t sa = sbase + (ch % 3)*(2*TILE_B);
        uint32_t sb = sa + TILE_B;
        #pragma unroll
        for (int ks = 0; ks < 2; ks++) {
            uint32_t bf[4][2];
            #pragma unroll
            for (int nt = 0; nt < 4; nt++) {
                uint32_t ba = sb + (wn*32 + nt*8 + bn_row)*PITCH_B + bn_col + ks*32;
                bf[nt][0] = lds32(ba);
                bf[nt][1] = lds32(ba + 16);
            }
            #pragma unroll
            for (int mt = 0; mt < 4; mt++) {
                uint32_t a0, a1, a2, a3;
                uint32_t aa = sa + (wr*64 + mt*16 + lm_row)*PITCH_B + lm_col + ks*32;
                ldmatrix_x4(a0, a1, a2, a3, aa);
                #pragma unroll
                for (int nt = 0; nt < 4; nt++)
                    mma16816(acc[mt][nt], a0, a1, a2, a3, bf[nt][0], bf[nt][1]);
            }
        }
    }
#undef ISSUE

    int mrow = lane >> 2;
    int ncol = (lane & 3) * 2;
    #pragma unroll
    for (int mt = 0; mt < 4; mt++) {
        int o = o0 + wr*64 + mt*16 + mrow;
        float bb0 = bref[o], bb1 = bref[o + 8];
        #pragma unroll
        for (int nt = 0; nt < 4; nt++) {
            int p = p0 + wn*32 + nt*8 + ncol;
            float2 gg = *(const float2*)&g_g[bz*HWn + p];
            float2 r0, r1;
            r0.x = acc[mt][nt][0] + bb0*gg.x;
            r0.y = acc[mt][nt][1] + bb0*gg.y;
            r1.x = acc[mt][nt][2] + bb1*gg.x;
            r1.y = acc[mt][nt][3] + bb1*gg.y;
            *(float2*)&out[((size_t)(bz*Cn + o))     * HWn + p] = r0;
            *(float2*)&out[((size_t)(bz*Cn + o + 8)) * HWn + p] = r1;
        }
    }
}

// ============================================================
extern "C" void kernel_launch(void* const* d_in, const int* in_sizes, int n_in,
                              void* d_out, int out_size) {
    const float* query   = (const float*)d_in[0];
    const float* key     = (const float*)d_in[1];
    const float* gmb     = (const float*)d_in[2];
    const float* w_refer = (const float*)d_in[3];
    const float* b_refer = (const float*)d_in[4];
    const float* w_attn  = (const float*)d_in[5];
    const float* b_attn  = (const float*)d_in[6];
    const float* w_mask  = (const float*)d_in[7];
    const float* b_mask  = (const float*)d_in[8];
    const float* w_off   = (const float*)d_in[9];
    const float* b_off   = (const float*)d_in[10];
    const unsigned* temp = (const unsigned*)d_in[11];
    float* out = (float*)d_out;

    static int attr_set = 0;
    if (!attr_set) {
        cudaFuncSetAttribute(k_gemm_mma, cudaFuncAttributeMaxDynamicSharedMemorySize,
                             GEMM_SMEM);
        cudaFuncSetAttribute(k_gather, cudaFuncAttributeMaxDynamicSharedMemorySize,
                             GATHER_SMEM);
        attr_set = 1;
    }

    k_transpose<<<dim3(HWn/32, Cn/32, Bn), dim3(32, 8)>>>(key);
    k_params<<<NPIX/128, 256>>>(query, gmb, b_attn, b_mask, b_off,
                                w_attn, w_mask, w_off, temp);
    k_wsplit<<<Cn*Cn/256, 256>>>(w_refer);
    k_gather<<<dim3(Hn, Bn, 4), 256, GATHER_SMEM>>>();
    k_gemm_mma<<<dim3(HWn/128, Cn/128, Bn), 256, GEMM_SMEM>>>(b_refer, out);
}

// round 13
// speedup vs baseline: 1.3390x; 1.0022x over previous
#include <cuda_runtime.h>
#include <cuda_bf16.h>
#include <cstdint>

#define Bn   8
#define Cn   256
#define Kn   9
#define Hn   64
#define Wn   64
#define HWn  (Hn*Wn)       // 4096
#define NPIX (Bn*HWn)      // 32768
#define OVC  8             // overflow taps per pixel (far taps, rare)

// ---- scratch (device globals; no allocation allowed) ----
__device__ float g_key_t[(size_t)Bn*HWn*Cn];   // [B][HW][C] transposed key
__device__ float g_s[(size_t)NPIX*Cn];         // sampled features (tf32-rounded fp32)
__device__ float g_wt[Cn*Cn];                  // w_refer (tf32-rounded fp32)
__device__ float g_w9[9*NPIX];                 // dense 3x3 stencil [j][pix]
__device__ float g_ovw[NPIX*OVC];              // overflow weights
__device__ int   g_ovi[NPIX*OVC];              // overflow hw idx
__device__ int   g_ovn[NPIX];                  // overflow counts
__device__ float g_g[NPIX];                    // bias weight-sum per pixel

// ================= helpers =================
__device__ __forceinline__ uint32_t smem_u32(const void* p) {
    uint32_t a;
    asm("{ .reg .u64 t; cvta.to.shared.u64 t, %1; cvt.u32.u64 %0, t; }" : "=r"(a) : "l"(p));
    return a;
}
__device__ __forceinline__ uint32_t lds32(uint32_t a) {
    uint32_t v;
    asm volatile("ld.shared.b32 %0, [%1];" : "=r"(v) : "r"(a));
    return v;
}
__device__ __forceinline__ float tf32r(float x) {
    uint32_t r;
    asm("cvt.rna.tf32.f32 %0, %1;" : "=r"(r) : "f"(x));
    return __uint_as_float(r);
}
__device__ __forceinline__ void mma_tf32(float* c,
                                         uint32_t a0, uint32_t a1, uint32_t a2, uint32_t a3,
                                         uint32_t b0, uint32_t b1) {
    asm volatile(
        "mma.sync.aligned.m16n8k8.row.col.f32.tf32.tf32.f32 "
        "{%0,%1,%2,%3}, {%4,%5,%6,%7}, {%8,%9}, {%0,%1,%2,%3};"
        : "+f"(c[0]), "+f"(c[1]), "+f"(c[2]), "+f"(c[3])
        : "r"(a0), "r"(a1), "r"(a2), "r"(a3), "r"(b0), "r"(b1));
}
__device__ __forceinline__ void cp16(uint32_t s, const void* g) {
    asm volatile("cp.async.cg.shared.global [%0], [%1], 16;" :: "r"(s), "l"(g));
}
__device__ __forceinline__ void cp_commit() {
    asm volatile("cp.async.commit_group;" ::: "memory");
}
template<int N> __device__ __forceinline__ void cp_wait() {
    asm volatile("cp.async.wait_group %0;" :: "n"(N) : "memory");
}

// ============================================================
// K1 (fused prep): blockIdx dispatch
//   [0, 8192)    : transpose key [B,C,HW] -> g_key_t [B,HW,C]
//   [8192, 8448) : params + softmaxes + dense 3x3 stencil fold
//   [8448, 8704) : w_refer -> g_wt (tf32 round)
// ============================================================
#define PREP_TRANS  8192
#define PREP_PARAMS 8448
#define PREP_TOTAL  8704

__global__ void __launch_bounds__(256)
k_prep(const float* __restrict__ query,
       const float* __restrict__ key,
       const float* __restrict__ w_refer,
       const float* __restrict__ gmb,
       const float* __restrict__ b_attn,
       const float* __restrict__ b_mask,
       const float* __restrict__ b_off,
       const float* __restrict__ w_attn,
       const float* __restrict__ w_mask,
       const float* __restrict__ w_off,
       const unsigned* __restrict__ temp_raw) {
    __shared__ __align__(16) char sm[44032];
    int bid = blockIdx.x;
    int tid = threadIdx.x;

    if (bid < PREP_TRANS) {
        // ---- transpose ----
        float (*t)[33] = (float(*)[33])sm;
        int x   = bid & 127;
        int yc  = (bid >> 7) & 7;
        int b   = bid >> 10;
        int hw0 = x * 32;
        int c0  = yc * 32;
        int tx = tid & 31, ty = tid >> 5;
        const float* src = key + (size_t)b * Cn * HWn;
        #pragma unroll
        for (int i = 0; i < 4; i++)
            t[ty + i*8][tx] = src[(size_t)(c0 + ty + i*8) * HWn + hw0 + tx];
        __syncthreads();
        float* dst = g_key_t + (size_t)b * HWn * Cn;
        #pragma unroll
        for (int i = 0; i < 4; i++)
            dst[(size_t)(hw0 + ty + i*8) * Cn + c0 + tx] = t[tx][ty + i*8];
        return;
    }
    if (bid >= PREP_PARAMS) {
        // ---- w convert ----
        int i = (bid - PREP_PARAMS) * 256 + tid;
        g_wt[i] = tf32r(w_refer[i]);
        return;
    }

    // ---- params ----
    float4* sW    = (float4*)sm;             // 28672 B
    float*  sB    = (float*)(sm + 28672);    // 128 B
    float*  sPart = (float*)(sm + 28800);    // 14848 B
    for (int i = tid; i < 576; i += 256) sW[i]        = ((const float4*)w_attn)[i];
    for (int i = tid; i < 576; i += 256) sW[576 + i]  = ((const float4*)w_mask)[i];
    for (int i = tid; i < 640; i += 256) sW[1152 + i] = ((const float4*)w_off)[i];
    if (tid < 9)  { sB[tid] = b_attn[tid]; sB[9 + tid] = b_mask[tid]; }
    if (tid < 10) sB[18 + tid] = b_off[tid];
    __syncthreads();

    int lp = tid & 127, ph = tid >> 7;
    int pix = (bid - PREP_TRANS) * 128 + lp;
    int b  = pix >> 12;
    int hw = pix & (HWn - 1);

    const float* q = query + (size_t)b * Cn * HWn + (size_t)(ph*128) * HWn + hw;
    float acc[28];
    #pragma unroll
    for (int r = 0; r < 28; r++) acc[r] = 0.f;

    #pragma unroll 4
    for (int c4 = 0; c4 < 32; c4++) {
        float q0 = q[(c4*4 + 0) * HWn];
        float q1 = q[(c4*4 + 1) * HWn];
        float q2 = q[(c4*4 + 2) * HWn];
        float q3 = q[(c4*4 + 3) * HWn];
        #pragma unroll
        for (int r = 0; r < 28; r++) {
            float4 w = sW[r*64 + ph*32 + c4];
            acc[r] += q0*w.x + q1*w.y + q2*w.z + q3*w.w;
        }
    }

    if (ph == 1) {
        #pragma unroll
        for (int r = 0; r < 28; r++) sPart[lp*29 + r] = acc[r];
    }
    __syncthreads();
    if (ph == 1) return;

    #pragma unroll
    for (int r = 0; r < 28; r++) acc[r] += sPart[lp*29 + r];

    unsigned lo = temp_raw[0];
    float t;
    if      (lo == 1u)           t = 1.f;
    else if (lo == 0x3F800000u)  t = 1.f;
    else if (lo == 0u)           t = 1.f;
    else                         t = __uint_as_float(lo);
    float invt = 1.f / t;

    float mv[9]; float mx = -3.4e38f;
    #pragma unroll
    for (int k = 0; k < 9; k++) {
        float gk = gmb[(size_t)(b*Kn + k) * HWn + hw];
        mv[k] = (acc[9 + k] + sB[9 + k] + gk) * invt;
        mx = fmaxf(mx, mv[k]);
    }
    float sum = 0.f;
    #pragma unroll
    for (int k = 0; k < 9; k++) { mv[k] = expf(mv[k] - mx); sum += mv[k]; }
    float rs = 1.f / sum;

    float z[9]; float mx2 = -3.4e38f;
    #pragma unroll
    for (int k = 0; k < 9; k++) {
        z[k] = (acc[k] + sB[k]) * (mv[k] * rs);
        mx2 = fmaxf(mx2, z[k]);
    }
    float sum2 = 0.f;
    #pragma unroll
    for (int k = 0; k < 9; k++) { z[k] = expf(z[k] - mx2); sum2 += z[k]; }
    float rs2 = 1.f / sum2;

    // dense 3x3 stencil fold
    int py0 = hw >> 6, px0 = hw & 63;
    float w9[9];
    #pragma unroll
    for (int i = 0; i < 9; i++) w9[i] = 0.f;
    float gs = 0.f; int cnt = 0;

    #pragma unroll
    for (int k = 0; k < 9; k++) {
        float aw = z[k] * rs2;
        float dy = acc[18 + k] + sB[18 + k];
        float dx = acc[19 + k] + sB[19 + k];
        float py = (float)py0 + dy;
        float px = (float)px0 + dx;
        float y0f = floorf(py), x0f = floorf(px);
        float wy = py - y0f, wx = px - x0f;
        int y0 = (int)y0f, x0 = (int)x0f;
        float ws[4] = {(1.f-wy)*(1.f-wx), (1.f-wy)*wx, wy*(1.f-wx), wy*wx};
        int   yy[4] = {y0, y0, y0+1, y0+1};
        int   xx[4] = {x0, x0+1, x0, x0+1};
        #pragma unroll
        for (int t4 = 0; t4 < 4; t4++) {
            bool v = (yy[t4] >= 0) & (yy[t4] < Hn) & (xx[t4] >= 0) & (xx[t4] < Wn);
            float w = ws[t4] * aw;
            if (!v || w == 0.f) continue;
            gs += w;
            int sy = yy[t4] - (py0 - 1);
            int sx = xx[t4] - (px0 - 1);
            if (sy >= 0 && sy < 3 && sx >= 0 && sx < 3) {
                int s9 = sy*3 + sx;
                #pragma unroll
                for (int s = 0; s < 9; s++)
                    w9[s] += (s9 == s) ? w : 0.f;
            } else if (cnt < OVC) {
                g_ovw[pix*OVC + cnt] = w;
                g_ovi[pix*OVC + cnt] = yy[t4]*Wn + xx[t4];
                cnt++;
            }
        }
    }
    g_ovn[pix] = cnt;
    g_g[pix]   = gs;
    #pragma unroll
    for (int j = 0; j < 9; j++) g_w9[j*NPIX + pix] = w9[j];
}

// ============================================================
// K2: STENCIL gather (as R11), output tf32-rounded fp32 into g_s
// ============================================================
#define GATHER_SMEM 51712

__global__ void __launch_bounds__(256, 4)
k_gather() {
    extern __shared__ __align__(16) char gsm[];
    float4* win4 = (float4*)gsm;
    float*  w9s  = (float*)(gsm + 49152);
    int*    nov  = (int*)(gsm + 51456);

    int y   = blockIdx.x;
    int b   = blockIdx.y;
    int cq  = blockIdx.z;        // 0..3 channel quarter
    int tid = threadIdx.x;
    int pixbase = b*HWn + y*Wn;
    const float4* kb4 = (const float4*)(g_key_t + (size_t)b * HWn * Cn);

    for (int i = tid; i < 576; i += 256) {
        int p = i / 9, j = i - p*9;
        w9s[i] = g_w9[j*NPIX + pixbase + p];
    }
    if (tid < 64) nov[tid] = g_ovn[pixbase + tid];

    float4 z4 = make_float4(0.f, 0.f, 0.f, 0.f);
    #pragma unroll
    for (int it = 0; it < 12; it++) {
        int i   = tid + it*256;
        int r   = i >> 10;
        int rem = i & 1023;
        int ry  = y - 1 + r;
        float4 v = z4;
        if (ry >= 0 && ry < Hn)
            v = kb4[((size_t)(ry*Wn) << 6) + ((rem >> 4) << 6) + cq*16 + (rem & 15)];
        win4[i] = v;
    }
    __syncthreads();

    int c4 = tid & 15;
    #pragma unroll
    for (int it = 0; it < 4; it++) {
        int p = (tid >> 4) + it*16;
        int cm1 = max(p - 1, 0), cp1 = min(p + 1, Wn - 1);
        int col16[3] = {cm1*16, p*16, cp1*16};
        float w9[9];
        #pragma unroll
        for (int i = 0; i < 9; i++) w9[i] = w9s[p*9 + i];

        float4 acc = make_float4(0.f, 0.f, 0.f, 0.f);
        #pragma unroll
        for (int k = 0; k < 9; k++) {
            float w = w9[k];
            float4 v = win4[(k/3)*1024 + col16[k%3] + c4];
            acc.x += w*v.x; acc.y += w*v.y; acc.z += w*v.z; acc.w += w*v.w;
        }
        int nv = nov[p];
        for (int j = 0; j < nv; j++) {
            int pix = pixbase + p;
            float w   = g_ovw[pix*OVC + j];
            int   hwt = g_ovi[pix*OVC + j];
            float4 v = kb4[hwt*64 + cq*16 + c4];
            acc.x += w*v.x; acc.y += w*v.y; acc.z += w*v.z; acc.w += w*v.w;
        }

        size_t base = ((size_t)(pixbase + p)) * Cn + cq*64 + c4*4;
        float4 o4;
        o4.x = tf32r(acc.x); o4.y = tf32r(acc.y);
        o4.z = tf32r(acc.z); o4.w = tf32r(acc.w);
        *(float4*)&g_s[base] = o4;
    }
}

// ============================================================
// K3: tf32 single-pass GEMM (mma.m16n8k8.tf32), 3-stage cp.async
//   D[o,p] = Wt . S^T   (K = 256)
// CTA 128x128, 8 warps (2x4), warp 64x32, K-chunk 32.
// SMEM pitch 36 floats -> all fragment lds are conflict-free.
// ============================================================
#define PITCH_F 36
#define TILE_FB (128*PITCH_F*4)      // 18432 B per operand tile
#define NCHUNK2 8
#define GEMM_SMEM (3*2*TILE_FB)      // 110592 B

__global__ void __launch_bounds__(256)
k_gemm_tf32(const float* __restrict__ bref, float* __restrict__ out) {
    extern __shared__ __align__(16) char gsmg[];
    int tid = threadIdx.x, wid = tid >> 5, lane = tid & 31;
    int p0 = blockIdx.x * 128;
    int o0 = blockIdx.y * 128;
    int bz = blockIdx.z;
    int wr = wid >> 2;           // 0..1 (m)
    int wn = wid & 3;            // 0..3 (n)
    int gid = lane >> 2;         // 0..7
    int tig = lane & 3;          // 0..3

    uint32_t sbase = smem_u32(gsmg);
    int rA = tid >> 1;           // row 0..127
    int pa = (tid & 1) * 64;     // byte part within 128B row

    float acc[4][4][4];
    #pragma unroll
    for (int i = 0; i < 4; i++)
        #pragma unroll
        for (int j = 0; j < 4; j++)
            #pragma unroll
            for (int r = 0; r < 4; r++) acc[i][j][r] = 0.f;

#define ISSUE2(CH) do { \
        int _st = (CH) % 3, _c0 = (CH) * 32; \
        const char* _Ag = (const char*)(g_wt + (size_t)(o0 + rA)*Cn + _c0) + pa; \
        const char* _Bg = (const char*)(g_s + ((size_t)(bz*HWn + p0 + rA))*Cn + _c0) + pa; \
        uint32_t _sa = sbase + _st*(2*TILE_FB) + rA*(PITCH_F*4) + pa; \
        uint32_t _sb = _sa + TILE_FB; \
        cp16(_sa,      _Ag);      cp16(_sa + 16, _Ag + 16); \
        cp16(_sa + 32, _Ag + 32); cp16(_sa + 48, _Ag + 48); \
        cp16(_sb,      _Bg);      cp16(_sb + 16, _Bg + 16); \
        cp16(_sb + 32, _Bg + 32); cp16(_sb + 48, _Bg + 48); \
        cp_commit(); \
    } while (0)

    ISSUE2(0);
    ISSUE2(1);

    for (int ch = 0; ch < NCHUNK2; ch++) {
        if (ch == NCHUNK2 - 1) cp_wait<0>(); else cp_wait<1>();
        __syncthreads();
        if (ch + 2 < NCHUNK2) ISSUE2(ch + 2);

        uint32_t sa = sbase + (ch % 3)*(2*TILE_FB);
        uint32_t sb = sa + TILE_FB;
        #pragma unroll
        for (int ks = 0; ks < 4; ks++) {
            int k0 = ks*8;
            uint32_t bf[4][2];
            #pragma unroll
            for (int nt = 0; nt < 4; nt++) {
                uint32_t ba = sb + (((wn*32 + nt*8 + gid)*PITCH_F + k0 + tig) << 2);
                bf[nt][0] = lds32(ba);
                bf[nt][1] = lds32(ba + 16);
            }
            #pragma unroll
            for (int mt = 0; mt < 4; mt++) {
                uint32_t aa = sa + (((wr*64 + mt*16 + gid)*PITCH_F + k0 + tig) << 2);
                uint32_t a0 = lds32(aa);
                uint32_t a1 = lds32(aa + 8*PITCH_F*4);
                uint32_t a2 = lds32(aa + 16);
                uint32_t a3 = lds32(aa + 8*PITCH_F*4 + 16);
                #pragma unroll
                for (int nt = 0; nt < 4; nt++)
                    mma_tf32(acc[mt][nt], a0, a1, a2, a3, bf[nt][0], bf[nt][1]);
            }
        }
    }
#undef ISSUE2

    // epilogue: m16n8 C layout
    int mrow = lane >> 2;
    int ncol = (lane & 3) * 2;
    #pragma unroll
    for (int mt = 0; mt < 4; mt++) {
        int o = o0 + wr*64 + mt*16 + mrow;
        float bb0 = bref[o], bb1 = bref[o + 8];
        #pragma unroll
        for (int nt = 0; nt < 4; nt++) {
            int p = p0 + wn*32 + nt*8 + ncol;
            float2 gg = *(const float2*)&g_g[bz*HWn + p];
            float2 r0, r1;
            r0.x = acc[mt][nt][0] + bb0*gg.x;
            r0.y = acc[mt][nt][1] + bb0*gg.y;
            r1.x = acc[mt][nt][2] + bb1*gg.x;
            r1.y = acc[mt][nt][3] + bb1*gg.y;
            *(float2*)&out[((size_t)(bz*Cn + o))     * HWn + p] = r0;
            *(float2*)&out[((size_t)(bz*Cn + o + 8)) * HWn + p] = r1;
        }
    }
}

// ============================================================
extern "C" void kernel_launch(void* const* d_in, const int* in_sizes, int n_in,
                              void* d_out, int out_size) {
    const float* query   = (const float*)d_in[0];
    const float* key     = (const float*)d_in[1];
    const float* gmb     = (const float*)d_in[2];
    const float* w_refer = (const float*)d_in[3];
    const float* b_refer = (const float*)d_in[4];
    const float* w_attn  = (const float*)d_in[5];
    const float* b_attn  = (const float*)d_in[6];
    const float* w_mask  = (const float*)d_in[7];
    const float* b_mask  = (const float*)d_in[8];
    const float* w_off   = (const float*)d_in[9];
    const float* b_off   = (const float*)d_in[10];
    const unsigned* temp = (const unsigned*)d_in[11];
    float* out = (float*)d_out;

    static int attr_set = 0;
    if (!attr_set) {
        cudaFuncSetAttribute(k_gemm_tf32, cudaFuncAttributeMaxDynamicSharedMemorySize,
                             GEMM_SMEM);
        cudaFuncSetAttribute(k_gather, cudaFuncAttributeMaxDynamicSharedMemorySize,
                             GATHER_SMEM);
        attr_set = 1;
    }

    k_prep<<<PREP_TOTAL, 256>>>(query, key, w_refer, gmb,
                                b_attn, b_mask, b_off,
                                w_attn, w_mask, w_off, temp);
    k_gather<<<dim3(Hn, Bn, 4), 256, GATHER_SMEM>>>();
    k_gemm_tf32<<<dim3(HWn/128, Cn/128, Bn), 256, GEMM_SMEM>>>(b_refer, out);
}

// round 14
// speedup vs baseline: 1.4543x; 1.0860x over previous
#include <cuda_runtime.h>
#include <cuda_bf16.h>
#include <cstdint>

#define Bn   8
#define Cn   256
#define Kn   9
#define Hn   64
#define Wn   64
#define HWn  (Hn*Wn)       // 4096
#define NPIX (Bn*HWn)      // 32768
#define OVC  8             // overflow taps per pixel (far taps, rare)

// ---- scratch (device globals; no allocation allowed) ----
__device__ float g_key_t[(size_t)Bn*HWn*Cn];   // [B][HW][C] transposed key
__device__ float g_s[(size_t)NPIX*Cn];         // sampled features (tf32-rounded fp32)
__device__ float g_wt[Cn*Cn];                  // w_refer (tf32-rounded fp32)
__device__ float g_w9[9*NPIX];                 // dense 3x3 stencil [j][pix]
__device__ float g_ovw[NPIX*OVC];              // overflow weights
__device__ int   g_ovi[NPIX*OVC];              // overflow hw idx
__device__ int   g_ovn[NPIX];                  // overflow counts
__device__ float g_g[NPIX];                    // bias weight-sum per pixel

// ================= helpers =================
__device__ __forceinline__ uint32_t smem_u32(const void* p) {
    uint32_t a;
    asm("{ .reg .u64 t; cvta.to.shared.u64 t, %1; cvt.u32.u64 %0, t; }" : "=r"(a) : "l"(p));
    return a;
}
__device__ __forceinline__ uint32_t lds32(uint32_t a) {
    uint32_t v;
    asm volatile("ld.shared.b32 %0, [%1];" : "=r"(v) : "r"(a));
    return v;
}
__device__ __forceinline__ float tf32r(float x) {
    uint32_t r;
    asm("cvt.rna.tf32.f32 %0, %1;" : "=r"(r) : "f"(x));
    return __uint_as_float(r);
}
__device__ __forceinline__ void mma_tf32(float* c,
                                         uint32_t a0, uint32_t a1, uint32_t a2, uint32_t a3,
                                         uint32_t b0, uint32_t b1) {
    asm volatile(
        "mma.sync.aligned.m16n8k8.row.col.f32.tf32.tf32.f32 "
        "{%0,%1,%2,%3}, {%4,%5,%6,%7}, {%8,%9}, {%0,%1,%2,%3};"
        : "+f"(c[0]), "+f"(c[1]), "+f"(c[2]), "+f"(c[3])
        : "r"(a0), "r"(a1), "r"(a2), "r"(a3), "r"(b0), "r"(b1));
}
__device__ __forceinline__ void cp16(uint32_t s, const void* g) {
    asm volatile("cp.async.cg.shared.global [%0], [%1], 16;" :: "r"(s), "l"(g));
}
__device__ __forceinline__ void cp_commit() {
    asm volatile("cp.async.commit_group;" ::: "memory");
}
template<int N> __device__ __forceinline__ void cp_wait() {
    asm volatile("cp.async.wait_group %0;" :: "n"(N) : "memory");
}

// ============================================================
// K1a: transpose key [B,C,HW] -> g_key_t [B,HW,C]  (+ w tf32 cvt)
// Low-resource kernel: 4.2KB smem, ~32 regs -> high occupancy.
//   [0, 8192)    : transpose tiles
//   [8192, 8448) : w_refer -> g_wt
// ============================================================
#define TW_TRANS 8192
#define TW_TOTAL 8448

__global__ void __launch_bounds__(256)
k_trans_w(const float* __restrict__ key, const float* __restrict__ w_refer) {
    __shared__ float t[32][33];
    int bid = blockIdx.x;
    int tid = threadIdx.x;

    if (bid >= TW_TRANS) {
        int i = (bid - TW_TRANS) * 256 + tid;
        g_wt[i] = tf32r(w_refer[i]);
        return;
    }

    int x   = bid & 127;
    int yc  = (bid >> 7) & 7;
    int b   = bid >> 10;
    int hw0 = x * 32;
    int c0  = yc * 32;
    int tx = tid & 31, ty = tid >> 5;
    const float* src = key + (size_t)b * Cn * HWn;
    #pragma unroll
    for (int i = 0; i < 4; i++)
        t[ty + i*8][tx] = src[(size_t)(c0 + ty + i*8) * HWn + hw0 + tx];
    __syncthreads();
    float* dst = g_key_t + (size_t)b * HWn * Cn;
    #pragma unroll
    for (int i = 0; i < 4; i++)
        dst[(size_t)(hw0 + ty + i*8) * Cn + c0 + tx] = t[tx][ty + i*8];
}

// ============================================================
// K1b: params + softmaxes + dense 3x3 stencil fold.
// Block = 128 pixels, 256 threads, split-C reduction.
// ============================================================
__global__ void __launch_bounds__(256)
k_params(const float* __restrict__ query,
         const float* __restrict__ gmb,
         const float* __restrict__ b_attn,
         const float* __restrict__ b_mask,
         const float* __restrict__ b_off,
         const float* __restrict__ w_attn,
         const float* __restrict__ w_mask,
         const float* __restrict__ w_off,
         const unsigned* __restrict__ temp_raw) {
    __shared__ float4 sW[28*64];
    __shared__ float  sB[28];
    __shared__ float  sPart[128*29];
    int tid = threadIdx.x;
    for (int i = tid; i < 576; i += 256) sW[i]        = ((const float4*)w_attn)[i];
    for (int i = tid; i < 576; i += 256) sW[576 + i]  = ((const float4*)w_mask)[i];
    for (int i = tid; i < 640; i += 256) sW[1152 + i] = ((const float4*)w_off)[i];
    if (tid < 9)  { sB[tid] = b_attn[tid]; sB[9 + tid] = b_mask[tid]; }
    if (tid < 10) sB[18 + tid] = b_off[tid];
    __syncthreads();

    int lp = tid & 127, ph = tid >> 7;
    int pix = blockIdx.x * 128 + lp;
    int b  = pix >> 12;
    int hw = pix & (HWn - 1);

    const float* q = query + (size_t)b * Cn * HWn + (size_t)(ph*128) * HWn + hw;
    float acc[28];
    #pragma unroll
    for (int r = 0; r < 28; r++) acc[r] = 0.f;

    #pragma unroll 4
    for (int c4 = 0; c4 < 32; c4++) {
        float q0 = q[(c4*4 + 0) * HWn];
        float q1 = q[(c4*4 + 1) * HWn];
        float q2 = q[(c4*4 + 2) * HWn];
        float q3 = q[(c4*4 + 3) * HWn];
        #pragma unroll
        for (int r = 0; r < 28; r++) {
            float4 w = sW[r*64 + ph*32 + c4];
            acc[r] += q0*w.x + q1*w.y + q2*w.z + q3*w.w;
        }
    }

    if (ph == 1) {
        #pragma unroll
        for (int r = 0; r < 28; r++) sPart[lp*29 + r] = acc[r];
    }
    __syncthreads();
    if (ph == 1) return;

    #pragma unroll
    for (int r = 0; r < 28; r++) acc[r] += sPart[lp*29 + r];

    unsigned lo = temp_raw[0];
    float t;
    if      (lo == 1u)           t = 1.f;
    else if (lo == 0x3F800000u)  t = 1.f;
    else if (lo == 0u)           t = 1.f;
    else                         t = __uint_as_float(lo);
    float invt = 1.f / t;

    float mv[9]; float mx = -3.4e38f;
    #pragma unroll
    for (int k = 0; k < 9; k++) {
        float gk = gmb[(size_t)(b*Kn + k) * HWn + hw];
        mv[k] = (acc[9 + k] + sB[9 + k] + gk) * invt;
        mx = fmaxf(mx, mv[k]);
    }
    float sum = 0.f;
    #pragma unroll
    for (int k = 0; k < 9; k++) { mv[k] = expf(mv[k] - mx); sum += mv[k]; }
    float rs = 1.f / sum;

    float z[9]; float mx2 = -3.4e38f;
    #pragma unroll
    for (int k = 0; k < 9; k++) {
        z[k] = (acc[k] + sB[k]) * (mv[k] * rs);
        mx2 = fmaxf(mx2, z[k]);
    }
    float sum2 = 0.f;
    #pragma unroll
    for (int k = 0; k < 9; k++) { z[k] = expf(z[k] - mx2); sum2 += z[k]; }
    float rs2 = 1.f / sum2;

    // dense 3x3 stencil fold
    int py0 = hw >> 6, px0 = hw & 63;
    float w9[9];
    #pragma unroll
    for (int i = 0; i < 9; i++) w9[i] = 0.f;
    float gs = 0.f; int cnt = 0;

    #pragma unroll
    for (int k = 0; k < 9; k++) {
        float aw = z[k] * rs2;
        float dy = acc[18 + k] + sB[18 + k];
        float dx = acc[19 + k] + sB[19 + k];
        float py = (float)py0 + dy;
        float px = (float)px0 + dx;
        float y0f = floorf(py), x0f = floorf(px);
        float wy = py - y0f, wx = px - x0f;
        int y0 = (int)y0f, x0 = (int)x0f;
        float ws[4] = {(1.f-wy)*(1.f-wx), (1.f-wy)*wx, wy*(1.f-wx), wy*wx};
        int   yy[4] = {y0, y0, y0+1, y0+1};
        int   xx[4] = {x0, x0+1, x0, x0+1};
        #pragma unroll
        for (int t4 = 0; t4 < 4; t4++) {
            bool v = (yy[t4] >= 0) & (yy[t4] < Hn) & (xx[t4] >= 0) & (xx[t4] < Wn);
            float w = ws[t4] * aw;
            if (!v || w == 0.f) continue;
            gs += w;
            int sy = yy[t4] - (py0 - 1);
            int sx = xx[t4] - (px0 - 1);
            if (sy >= 0 && sy < 3 && sx >= 0 && sx < 3) {
                int s9 = sy*3 + sx;
                #pragma unroll
                for (int s = 0; s < 9; s++)
                    w9[s] += (s9 == s) ? w : 0.f;
            } else if (cnt < OVC) {
                g_ovw[pix*OVC + cnt] = w;
                g_ovi[pix*OVC + cnt] = yy[t4]*Wn + xx[t4];
                cnt++;
            }
        }
    }
    g_ovn[pix] = cnt;
    g_g[pix]   = gs;
    #pragma unroll
    for (int j = 0; j < 9; j++) g_w9[j*NPIX + pix] = w9[j];
}

// ============================================================
// K2: STENCIL gather, output tf32-rounded fp32 into g_s
// ============================================================
#define GATHER_SMEM 51712

__global__ void __launch_bounds__(256, 4)
k_gather() {
    extern __shared__ __align__(16) char gsm[];
    float4* win4 = (float4*)gsm;
    float*  w9s  = (float*)(gsm + 49152);
    int*    nov  = (int*)(gsm + 51456);

    int y   = blockIdx.x;
    int b   = blockIdx.y;
    int cq  = blockIdx.z;        // 0..3 channel quarter
    int tid = threadIdx.x;
    int pixbase = b*HWn + y*Wn;
    const float4* kb4 = (const float4*)(g_key_t + (size_t)b * HWn * Cn);

    for (int i = tid; i < 576; i += 256) {
        int p = i / 9, j = i - p*9;
        w9s[i] = g_w9[j*NPIX + pixbase + p];
    }
    if (tid < 64) nov[tid] = g_ovn[pixbase + tid];

    float4 z4 = make_float4(0.f, 0.f, 0.f, 0.f);
    #pragma unroll
    for (int it = 0; it < 12; it++) {
        int i   = tid + it*256;
        int r   = i >> 10;
        int rem = i & 1023;
        int ry  = y - 1 + r;
        float4 v = z4;
        if (ry >= 0 && ry < Hn)
            v = kb4[((size_t)(ry*Wn) << 6) + ((rem >> 4) << 6) + cq*16 + (rem & 15)];
        win4[i] = v;
    }
    __syncthreads();

    int c4 = tid & 15;
    #pragma unroll
    for (int it = 0; it < 4; it++) {
        int p = (tid >> 4) + it*16;
        int cm1 = max(p - 1, 0), cp1 = min(p + 1, Wn - 1);
        int col16[3] = {cm1*16, p*16, cp1*16};
        float w9[9];
        #pragma unroll
        for (int i = 0; i < 9; i++) w9[i] = w9s[p*9 + i];

        float4 acc = make_float4(0.f, 0.f, 0.f, 0.f);
        #pragma unroll
        for (int k = 0; k < 9; k++) {
            float w = w9[k];
            float4 v = win4[(k/3)*1024 + col16[k%3] + c4];
            acc.x += w*v.x; acc.y += w*v.y; acc.z += w*v.z; acc.w += w*v.w;
        }
        int nv = nov[p];
        for (int j = 0; j < nv; j++) {
            int pix = pixbase + p;
            float w   = g_ovw[pix*OVC + j];
            int   hwt = g_ovi[pix*OVC + j];
            float4 v = kb4[hwt*64 + cq*16 + c4];
            acc.x += w*v.x; acc.y += w*v.y; acc.z += w*v.z; acc.w += w*v.w;
        }

        size_t base = ((size_t)(pixbase + p)) * Cn + cq*64 + c4*4;
        float4 o4;
        o4.x = tf32r(acc.x); o4.y = tf32r(acc.y);
        o4.z = tf32r(acc.z); o4.w = tf32r(acc.w);
        *(float4*)&g_s[base] = o4;
    }
}

// ============================================================
// K3: tf32 single-pass GEMM (mma.m16n8k8.tf32), 3-stage cp.async
//   D[o,p] = Wt . S^T   (K = 256)
// CTA 128x128, 8 warps (2x4), warp 64x32, K-chunk 32.
// SMEM pitch 36 floats -> all fragment lds are conflict-free.
// ============================================================
#define PITCH_F 36
#define TILE_FB (128*PITCH_F*4)      // 18432 B per operand tile
#define NCHUNK2 8
#define GEMM_SMEM (3*2*TILE_FB)      // 110592 B

__global__ void __launch_bounds__(256)
k_gemm_tf32(const float* __restrict__ bref, float* __restrict__ out) {
    extern __shared__ __align__(16) char gsmg[];
    int tid = threadIdx.x, wid = tid >> 5, lane = tid & 31;
    int p0 = blockIdx.x * 128;
    int o0 = blockIdx.y * 128;
    int bz = blockIdx.z;
    int wr = wid >> 2;           // 0..1 (m)
    int wn = wid & 3;            // 0..3 (n)
    int gid = lane >> 2;         // 0..7
    int tig = lane & 3;          // 0..3

    uint32_t sbase = smem_u32(gsmg);
    int rA = tid >> 1;           // row 0..127
    int pa = (tid & 1) * 64;     // byte part within 128B row

    float acc[4][4][4];
    #pragma unroll
    for (int i = 0; i < 4; i++)
        #pragma unroll
        for (int j = 0; j < 4; j++)
            #pragma unroll
            for (int r = 0; r < 4; r++) acc[i][j][r] = 0.f;

#define ISSUE2(CH) do { \
        int _st = (CH) % 3, _c0 = (CH) * 32; \
        const char* _Ag = (const char*)(g_wt + (size_t)(o0 + rA)*Cn + _c0) + pa; \
        const char* _Bg = (const char*)(g_s + ((size_t)(bz*HWn + p0 + rA))*Cn + _c0) + pa; \
        uint32_t _sa = sbase + _st*(2*TILE_FB) + rA*(PITCH_F*4) + pa; \
        uint32_t _sb = _sa + TILE_FB; \
        cp16(_sa,      _Ag);      cp16(_sa + 16, _Ag + 16); \
        cp16(_sa + 32, _Ag + 32); cp16(_sa + 48, _Ag + 48); \
        cp16(_sb,      _Bg);      cp16(_sb + 16, _Bg + 16); \
        cp16(_sb + 32, _Bg + 32); cp16(_sb + 48, _Bg + 48); \
        cp_commit(); \
    } while (0)

    ISSUE2(0);
    ISSUE2(1);

    for (int ch = 0; ch < NCHUNK2; ch++) {
        if (ch == NCHUNK2 - 1) cp_wait<0>(); else cp_wait<1>();
        __syncthreads();
        if (ch + 2 < NCHUNK2) ISSUE2(ch + 2);

        uint32_t sa = sbase + (ch % 3)*(2*TILE_FB);
        uint32_t sb = sa + TILE_FB;
        #pragma unroll
        for (int ks = 0; ks < 4; ks++) {
            int k0 = ks*8;
            uint32_t bf[4][2];
            #pragma unroll
            for (int nt = 0; nt < 4; nt++) {
                uint32_t ba = sb + (((wn*32 + nt*8 + gid)*PITCH_F + k0 + tig) << 2);
                bf[nt][0] = lds32(ba);
                bf[nt][1] = lds32(ba + 16);
            }
            #pragma unroll
            for (int mt = 0; mt < 4; mt++) {
                uint32_t aa = sa + (((wr*64 + mt*16 + gid)*PITCH_F + k0 + tig) << 2);
                uint32_t a0 = lds32(aa);
                uint32_t a1 = lds32(aa + 8*PITCH_F*4);
                uint32_t a2 = lds32(aa + 16);
                uint32_t a3 = lds32(aa + 8*PITCH_F*4 + 16);
                #pragma unroll
                for (int nt = 0; nt < 4; nt++)
                    mma_tf32(acc[mt][nt], a0, a1, a2, a3, bf[nt][0], bf[nt][1]);
            }
        }
    }
#undef ISSUE2

    // epilogue: m16n8 C layout
    int mrow = lane >> 2;
    int ncol = (lane & 3) * 2;
    #pragma unroll
    for (int mt = 0; mt < 4; mt++) {
        int o = o0 + wr*64 + mt*16 + mrow;
        float bb0 = bref[o], bb1 = bref[o + 8];
        #pragma unroll
        for (int nt = 0; nt < 4; nt++) {
            int p = p0 + wn*32 + nt*8 + ncol;
            float2 gg = *(const float2*)&g_g[bz*HWn + p];
            float2 r0, r1;
            r0.x = acc[mt][nt][0] + bb0*gg.x;
            r0.y = acc[mt][nt][1] + bb0*gg.y;
            r1.x = acc[mt][nt][2] + bb1*gg.x;
            r1.y = acc[mt][nt][3] + bb1*gg.y;
            *(float2*)&out[((size_t)(bz*Cn + o))     * HWn + p] = r0;
            *(float2*)&out[((size_t)(bz*Cn + o + 8)) * HWn + p] = r1;
        }
    }
}

// ============================================================
extern "C" void kernel_launch(void* const* d_in, const int* in_sizes, int n_in,
                              void* d_out, int out_size) {
    const float* query   = (const float*)d_in[0];
    const float* key     = (const float*)d_in[1];
    const float* gmb     = (const float*)d_in[2];
    const float* w_refer = (const float*)d_in[3];
    const float* b_refer = (const float*)d_in[4];
    const float* w_attn  = (const float*)d_in[5];
    const float* b_attn  = (const float*)d_in[6];
    const float* w_mask  = (const float*)d_in[7];
    const float* b_mask  = (const float*)d_in[8];
    const float* w_off   = (const float*)d_in[9];
    const float* b_off   = (const float*)d_in[10];
    const unsigned* temp = (const unsigned*)d_in[11];
    float* out = (float*)d_out;

    static int attr_set = 0;
    if (!attr_set) {
        cudaFuncSetAttribute(k_gemm_tf32, cudaFuncAttributeMaxDynamicSharedMemorySize,
                             GEMM_SMEM);
        cudaFuncSetAttribute(k_gather, cudaFuncAttributeMaxDynamicSharedMemorySize,
                             GATHER_SMEM);
        attr_set = 1;
    }

    k_trans_w<<<TW_TOTAL, 256>>>(key, w_refer);
    k_params<<<NPIX/128, 256>>>(query, gmb, b_attn, b_mask, b_off,
                                w_attn, w_mask, w_off, temp);
    k_gather<<<dim3(Hn, Bn, 4), 256, GATHER_SMEM>>>();
    k_gemm_tf32<<<dim3(HWn/128, Cn/128, Bn), 256, GEMM_SMEM>>>(b_refer, out);
}